// round 9
// baseline (speedup 1.0000x reference)
#include <cuda_runtime.h>
#include <cuda_bf16.h>
#include <math_constants.h>
#include <cstdint>

// Problem constants
#define BB    32
#define SS    512
#define MM    8
#define HH    512
#define KBIG  1536          // face|fc|img (label folded into pm)
#define DIM1_ 2048
#define WCOLS 2560
#define EPSF  1e-5f
#define BMS   (BB * MM * SS)

// GEMM tiling: CTA 128x256, warp tile 64x32, 16 warps (512 threads)
#define GM 128
#define GN 256
#define KC 64                        // bf16 k per chunk = 128 B/row
#define NCH (KBIG / KC)              // 24 chunks
#define A_TILE 16384                 // 128 rows x 128 B
#define B_TILE 32768                 // 256 rows x 128 B
#define STAGE_BYTES (2 * A_TILE + 2 * B_TILE)   // Ahi|Alo|Bhi|Blo = 96 KB
#define DYN_SMEM (2 * STAGE_BYTES + 1024)

// Scratch (device globals — no allocation allowed)
__device__ float g_pm[BB * MM * HH];           // part_mem + label part + b1
__device__ float g_ep[2 * BMS];                // partial logits per col-half
// Pre-converted bf16 hi/lo W1 slice
__device__ __nv_bfloat16 g_Whi[HH * KBIG];
__device__ __nv_bfloat16 g_Wlo[HH * KBIG];

__device__ __forceinline__ uint32_t smem_u32(const void* p) {
    return (uint32_t)__cvta_generic_to_shared(p);
}

#define LDMX4(r, addr) \
    asm volatile("ldmatrix.sync.aligned.m8n8.x4.shared.b16 {%0,%1,%2,%3}, [%4];" \
        : "=r"((r)[0]), "=r"((r)[1]), "=r"((r)[2]), "=r"((r)[3]) : "r"(addr))

#define MMA16816(d, a, b0v, b1v) \
    asm volatile("mma.sync.aligned.m16n8k16.row.col.f32.bf16.bf16.f32 " \
        "{%0,%1,%2,%3}, {%4,%5,%6,%7}, {%8,%9}, {%0,%1,%2,%3};" \
        : "+f"((d)[0]), "+f"((d)[1]), "+f"((d)[2]), "+f"((d)[3]) \
        : "r"((a)[0]), "r"((a)[1]), "r"((a)[2]), "r"((a)[3]), "r"(b0v), "r"(b1v))

#define CPASYNC(dst, src) \
    asm volatile("cp.async.cg.shared.global [%0], [%1], 16;" :: "r"(dst), "l"(src))
#define CPCOMMIT() asm volatile("cp.async.commit_group;" ::: "memory")
#define CPWAIT1()  asm volatile("cp.async.wait_group 1;" ::: "memory")
#define CPWAIT0()  asm volatile("cp.async.wait_group 0;" ::: "memory")

// 1-MUFU tanh (arch-agnostic PTX, sm_75+)
__device__ __forceinline__ float fast_tanh(float x) {
    float y;
    asm("tanh.approx.f32 %0, %1;" : "=f"(y) : "f"(x));
    return y;
}

// fp32x4 -> bf16 hi/lo pairs
__device__ __forceinline__ void cvt4(float4 v, uint2& hi, uint2& lo) {
    __nv_bfloat162 h0, h1, l0, l1;
    h0.x = __float2bfloat16_rn(v.x); h0.y = __float2bfloat16_rn(v.y);
    h1.x = __float2bfloat16_rn(v.z); h1.y = __float2bfloat16_rn(v.w);
    l0.x = __float2bfloat16_rn(v.x - __bfloat162float(h0.x));
    l0.y = __float2bfloat16_rn(v.y - __bfloat162float(h0.y));
    l1.x = __float2bfloat16_rn(v.z - __bfloat162float(h1.x));
    l1.y = __float2bfloat16_rn(v.w - __bfloat162float(h1.y));
    hi = make_uint2(*(uint32_t*)&h0, *(uint32_t*)&h1);
    lo = make_uint2(*(uint32_t*)&l0, *(uint32_t*)&l1);
}

// ---------------------------------------------------------------------------
// Kernel 0: fp32 -> bf16 hi/lo conversion of the W1 slice only.
// ---------------------------------------------------------------------------
#define W4 (HH * KBIG / 4)                   // 196608 float4s

__global__ __launch_bounds__(256)
void convert_w_kernel(const float* __restrict__ W1)
{
    const int idx = blockIdx.x * 256 + threadIdx.x;
    if (idx >= W4) return;
    const int h = idx / (KBIG / 4);
    const int k = (idx % (KBIG / 4)) * 4;
    uint2 hi, lo;
    cvt4(*(const float4*)&W1[(size_t)h * WCOLS + k], hi, lo);
    *(uint2*)&g_Whi[h * KBIG + k] = hi;
    *(uint2*)&g_Wlo[h * KBIG + k] = lo;
}

// ---------------------------------------------------------------------------
// Kernel 2: pm[b,m,h] = memory·W1mem + label·W1lab + b1   (runs BEFORE gemm)
// ---------------------------------------------------------------------------
__global__ __launch_bounds__(256)
void pm_kernel(const float* __restrict__ memory, const float* __restrict__ label,
               const float* __restrict__ W1, const float* __restrict__ b1)
{
    const int gw   = (blockIdx.x * blockDim.x + threadIdx.x) >> 5;
    const int lane = threadIdx.x & 31;
    const int h  = gw & (HH - 1);
    const int bm = gw >> 9;
    const int b  = bm >> 3;

    const float* __restrict__ wmem = W1 + (size_t)h * WCOLS + DIM1_;
    const float* __restrict__ wlab = W1 + (size_t)h * WCOLS + KBIG;
    const float* __restrict__ mrow = memory + (size_t)bm * HH;
    const float* __restrict__ lrow = label  + (size_t)b * 512;

    float acc = 0.f;
#pragma unroll 4
    for (int d = lane; d < HH; d += 32)
        acc = fmaf(wmem[d], mrow[d], fmaf(wlab[d], lrow[d], acc));
#pragma unroll
    for (int o = 16; o; o >>= 1) acc += __shfl_xor_sync(0xFFFFFFFFu, acc, o);
    if (lane == 0) g_pm[gw] = acc + b1[h];
}

// ---------------------------------------------------------------------------
// GEMM + fused e-epilogue.
// ---------------------------------------------------------------------------
__device__ __forceinline__ void load_B(uint32_t sb, int tid, int colBase, int kt)
{
#pragma unroll
    for (int i = 0; i < 4; i++) {
        const int v   = tid + i * 512;
        const int row = v >> 3;
        const int cs  = v & 7;
        const uint32_t off = (uint32_t)row * 128 + cs * 16;
        const uint32_t sw  = off ^ ((off >> 3) & 0x70);
        const size_t boff = (size_t)(colBase + row) * KBIG + kt * KC + cs * 8;
        CPASYNC(sb + 2 * A_TILE + sw,          (const char*)&g_Whi[boff]);
        CPASYNC(sb + 2 * A_TILE + B_TILE + sw, (const char*)&g_Wlo[boff]);
    }
}

__device__ __forceinline__ void load_A(float4 (&av)[4], int tid, int rowBase, int kt,
        const float* __restrict__ face, const float* __restrict__ fc,
        const float* __restrict__ img)
{
    const int f = kt >> 3;
    const float* src = (f == 0) ? face : (f == 1 ? fc : img);
    const int row = rowBase + (tid >> 2);
    const int col = (kt & 7) * KC + (tid & 3) * 16;
    const float* p = &src[(size_t)row * 512 + col];
#pragma unroll
    for (int j = 0; j < 4; j++) av[j] = *(const float4*)(p + j * 4);
}

__device__ __forceinline__ void sts_A(uint32_t sb, int tid, const float4 (&av)[4])
{
    const uint32_t rowoff = (uint32_t)(tid >> 2) * 128 + (tid & 3) * 32;
#pragma unroll
    for (int j = 0; j < 4; j++) {
        uint2 hi, lo;
        cvt4(av[j], hi, lo);
        const uint32_t off = rowoff + j * 8;
        const uint32_t sw  = off ^ ((off >> 3) & 0x70);
        *(uint2*)(uintptr_t)__cvta_shared_to_generic(sb + sw)          = hi;
        *(uint2*)(uintptr_t)__cvta_shared_to_generic(sb + A_TILE + sw) = lo;
    }
}

__device__ __forceinline__ void mma_stage(uint32_t sb, float (&d)[4][4][4],
        int mw, int nw, int a_r, int a_kh, int b_r, int b_kh)
{
#pragma unroll
    for (int ks = 0; ks < 4; ks++) {
        const uint32_t kb = (uint32_t)(ks * 2) * 16;

        uint32_t ah[4][4];
#pragma unroll
        for (int i = 0; i < 4; i++) {
            const uint32_t off = (uint32_t)(mw * 64 + i * 16 + a_r) * 128 + kb + a_kh * 16;
            LDMX4(ah[i], sb + (off ^ ((off >> 3) & 0x70)));
        }
        uint32_t bh[2][4];
#pragma unroll
        for (int p = 0; p < 2; p++) {
            const uint32_t off = (uint32_t)(nw * 32 + p * 16 + b_r) * 128 + kb + b_kh * 16;
            LDMX4(bh[p], sb + 2 * A_TILE + (off ^ ((off >> 3) & 0x70)));
        }
#pragma unroll
        for (int i = 0; i < 4; i++)
#pragma unroll
            for (int p = 0; p < 2; p++) {
                MMA16816(d[i][2 * p],     ah[i], bh[p][0], bh[p][1]);
                MMA16816(d[i][2 * p + 1], ah[i], bh[p][2], bh[p][3]);
            }
        {
            uint32_t bl[2][4];
#pragma unroll
            for (int p = 0; p < 2; p++) {
                const uint32_t off = (uint32_t)(nw * 32 + p * 16 + b_r) * 128 + kb + b_kh * 16;
                LDMX4(bl[p], sb + 2 * A_TILE + B_TILE + (off ^ ((off >> 3) & 0x70)));
            }
#pragma unroll
            for (int i = 0; i < 4; i++)
#pragma unroll
                for (int p = 0; p < 2; p++) {
                    MMA16816(d[i][2 * p],     ah[i], bl[p][0], bl[p][1]);
                    MMA16816(d[i][2 * p + 1], ah[i], bl[p][2], bl[p][3]);
                }
        }
        {
            uint32_t al[4][4];
#pragma unroll
            for (int i = 0; i < 4; i++) {
                const uint32_t off = (uint32_t)(mw * 64 + i * 16 + a_r) * 128 + kb + a_kh * 16;
                LDMX4(al[i], sb + A_TILE + (off ^ ((off >> 3) & 0x70)));
            }
#pragma unroll
            for (int i = 0; i < 4; i++)
#pragma unroll
                for (int p = 0; p < 2; p++) {
                    MMA16816(d[i][2 * p],     al[i], bh[p][0], bh[p][1]);
                    MMA16816(d[i][2 * p + 1], al[i], bh[p][2], bh[p][3]);
                }
        }
    }
}

__global__ __launch_bounds__(512, 1)
void gemm_pb_mma(const float* __restrict__ face, const float* __restrict__ fc,
                 const float* __restrict__ img,  const float* __restrict__ w2)
{
    extern __shared__ char dynsmem[];
    __shared__ float pm_s[MM][GN];   // pm slice for this CTA's col range
    __shared__ float w2_s[GN];

    const uint32_t dynaddr = smem_u32(dynsmem);
    const uint32_t sbase = (dynaddr + 1023) & ~1023u;

    const int tid  = threadIdx.x;
    const int warp = tid >> 5;
    const int lane = tid & 31;
    const int mw = warp >> 3;            // 0..1 : m offset mw*64
    const int nw = warp & 7;             // 0..7 : n offset nw*32
    const int colBase = blockIdx.x * GN;
    const int rowBase = blockIdx.y * GM;
    const int bb = rowBase >> 9;         // batch (128 | 512)
    const int s0 = rowBase & 511;

    const int a_r  = lane & 15;
    const int a_kh = lane >> 4;
    const int b_r  = (lane & 7) + ((lane >> 4) << 3);
    const int b_kh = (lane >> 3) & 1;

    // Load pm slice + w2 slice
    if (tid < GN) w2_s[tid] = w2[colBase + tid];
#pragma unroll
    for (int i = 0; i < 4; i++) {
        const int v = tid + i * 512;          // 2048 entries
        const int m = v >> 8, c = v & 255;
        pm_s[m][c] = g_pm[bb * (MM * HH) + m * HH + colBase + c];
    }

    float d[4][4][4];
#pragma unroll
    for (int i = 0; i < 4; i++)
#pragma unroll
        for (int j = 0; j < 4; j++)
#pragma unroll
            for (int q = 0; q < 4; q++) d[i][j][q] = 0.f;

    float4 av[4];
    load_A(av, tid, rowBase, 0, face, fc, img);
    load_B(sbase, tid, colBase, 0);
    CPCOMMIT();
    load_B(sbase + STAGE_BYTES, tid, colBase, 1);
    CPCOMMIT();
    sts_A(sbase, tid, av);
    load_A(av, tid, rowBase, 1, face, fc, img);

    for (int kt = 0; kt < NCH; kt++) {
        CPWAIT1();
        __syncthreads();
        if (kt + 1 < NCH) sts_A(sbase + ((kt + 1) & 1) * STAGE_BYTES, tid, av);
        if (kt + 2 < NCH) load_A(av, tid, rowBase, kt + 2, face, fc, img);
        mma_stage(sbase + (kt & 1) * STAGE_BYTES, d, mw, nw, a_r, a_kh, b_r, b_kh);
        __syncthreads();
        if (kt + 2 < NCH) load_B(sbase + (kt & 1) * STAGE_BYTES, tid, colBase, kt + 2);
        CPCOMMIT();
    }

    // ---------------- fused e epilogue ----------------
    CPWAIT0();
    __syncthreads();                       // stages dead; reuse dynsmem
    float* e_acc = (float*)dynsmem;        // [row][m*8+nw], row stride 65 (skew)
    for (int idx = tid; idx < 128 * 65; idx += 512) e_acc[idx] = 0.f;
    __syncthreads();

    const int g = lane >> 2;               // quad group: row within 16-tile
    const int cq = (lane & 3) * 2;         // base col within 8-col slot

#pragma unroll
    for (int i = 0; i < 4; i++) {
        float acc0[MM], acc1[MM];
#pragma unroll
        for (int m = 0; m < MM; m++) { acc0[m] = 0.f; acc1[m] = 0.f; }

#pragma unroll
        for (int nt = 0; nt < 4; nt++) {
#pragma unroll
            for (int q = 0; q < 4; q++) {
                const float v = d[i][nt][q];
                const int col = nw * 32 + nt * 8 + cq + (q & 1);
                const float wv = w2_s[col];
                float* acc = (q & 2) ? acc1 : acc0;
#pragma unroll
                for (int m = 0; m < MM; m++)
                    acc[m] = fmaf(wv, fast_tanh(v + pm_s[m][col]), acc[m]);
            }
        }
        // reduce over the quad (4 lanes share the same rows)
#pragma unroll
        for (int m = 0; m < MM; m++) {
            acc0[m] += __shfl_xor_sync(0xFFFFFFFFu, acc0[m], 1);
            acc0[m] += __shfl_xor_sync(0xFFFFFFFFu, acc0[m], 2);
            acc1[m] += __shfl_xor_sync(0xFFFFFFFFu, acc1[m], 1);
            acc1[m] += __shfl_xor_sync(0xFFFFFFFFu, acc1[m], 2);
        }
        if ((lane & 3) == 0) {
            const int row0 = mw * 64 + i * 16 + g;
#pragma unroll
            for (int m = 0; m < MM; m++) {
                e_acc[row0 * 65 + m * 8 + nw]       = acc0[m];
                e_acc[(row0 + 8) * 65 + m * 8 + nw] = acc1[m];
            }
        }
    }
    __syncthreads();

    // reduce nw (8 partials) and write partial-e for this col half
#pragma unroll
    for (int t = 0; t < 2; t++) {
        const int idx = tid * 2 + t;           // 0..1023
        const int row = idx >> 3;
        const int m   = idx & 7;
        const float* p = &e_acc[row * 65 + m * 8];
        float sum = 0.f;
#pragma unroll
        for (int j = 0; j < 8; j++) sum += p[j];
        g_ep[blockIdx.x * BMS + bb * (MM * SS) + m * SS + s0 + row] = sum;
    }
}

// ---------------------------------------------------------------------------
// Kernel 4: e = ep0+ep1, softmax over 4096, *mask, renorm.
// ---------------------------------------------------------------------------
__global__ __launch_bounds__(1024)
void softmax_kernel(const float* __restrict__ face_mask, float* __restrict__ alpha)
{
    __shared__ float sred[32];
    const int b = blockIdx.x;
    const int tid = threadIdx.x;
    const int w = tid >> 5, l = tid & 31;
    const float* __restrict__ e0 = g_ep + b * (MM * SS);
    const float* __restrict__ e1 = g_ep + BMS + b * (MM * SS);

    float v[4];
    float mx = -CUDART_INF_F;
#pragma unroll
    for (int i = 0; i < 4; i++) {
        const int idx = tid + i * 1024;
        v[i] = e0[idx] + e1[idx];
        mx = fmaxf(mx, v[i]);
    }

#pragma unroll
    for (int o = 16; o; o >>= 1) mx = fmaxf(mx, __shfl_xor_sync(0xFFFFFFFFu, mx, o));
    if (l == 0) sred[w] = mx;
    __syncthreads();
    if (tid < 32) {
        float t = sred[tid];
#pragma unroll
        for (int o = 16; o; o >>= 1) t = fmaxf(t, __shfl_xor_sync(0xFFFFFFFFu, t, o));
        if (tid == 0) sred[0] = t;
    }
    __syncthreads();
    mx = sred[0];
    __syncthreads();

    float sum = 0.f;
#pragma unroll
    for (int i = 0; i < 4; i++) { v[i] = __expf(v[i] - mx); sum += v[i]; }
#pragma unroll
    for (int o = 16; o; o >>= 1) sum += __shfl_xor_sync(0xFFFFFFFFu, sum, o);
    if (l == 0) sred[w] = sum;
    __syncthreads();
    if (tid < 32) {
        float t = sred[tid];
#pragma unroll
        for (int o = 16; o; o >>= 1) t += __shfl_xor_sync(0xFFFFFFFFu, t, o);
        if (tid == 0) sred[0] = t;
    }
    __syncthreads();
    const float Z = sred[0];
    __syncthreads();

    const float invZ = 1.f / Z;
    float msum = 0.f;
#pragma unroll
    for (int i = 0; i < 4; i++) {
        const int idx = tid + i * 1024;
        const float mk = face_mask[b * SS + (idx & 511)];
        v[i] = v[i] * invZ * mk;
        msum += v[i];
    }
#pragma unroll
    for (int o = 16; o; o >>= 1) msum += __shfl_xor_sync(0xFFFFFFFFu, msum, o);
    if (l == 0) sred[w] = msum;
    __syncthreads();
    if (tid < 32) {
        float t = sred[tid];
#pragma unroll
        for (int o = 16; o; o >>= 1) t += __shfl_xor_sync(0xFFFFFFFFu, t, o);
        if (tid == 0) sred[0] = t;
    }
    __syncthreads();
    const float inv = 1.f / (sred[0] + EPSF);

#pragma unroll
    for (int i = 0; i < 4; i++)
        alpha[b * (MM * SS) + tid + i * 1024] = v[i] * inv;
}

// ---------------------------------------------------------------------------
// Kernel 5: context[b,d] = sum_s (sum_m alpha[b,m,s]) * face[b,s,d]
// ---------------------------------------------------------------------------
__global__ __launch_bounds__(512)
void context_kernel(const float* __restrict__ face, const float* __restrict__ alpha,
                    float* __restrict__ ctx)
{
    __shared__ float asum[SS];
    const int b = blockIdx.x;
    const int tid = threadIdx.x;

    float a = 0.f;
#pragma unroll
    for (int m = 0; m < MM; m++) a += alpha[b * (MM * SS) + m * SS + tid];
    asum[tid] = a;
    __syncthreads();

    const float* __restrict__ fb = face + (size_t)b * SS * 512;
    float c0 = 0.f, c1 = 0.f, c2 = 0.f, c3 = 0.f;
    for (int s = 0; s < SS; s += 4) {
        c0 = fmaf(asum[s + 0], fb[(size_t)(s + 0) * 512 + tid], c0);
        c1 = fmaf(asum[s + 1], fb[(size_t)(s + 1) * 512 + tid], c1);
        c2 = fmaf(asum[s + 2], fb[(size_t)(s + 2) * 512 + tid], c2);
        c3 = fmaf(asum[s + 3], fb[(size_t)(s + 3) * 512 + tid], c3);
    }
    ctx[b * 512 + tid] = (c0 + c1) + (c2 + c3);
}

// ---------------------------------------------------------------------------
// Launch. Inputs: 0 fc, 1 img, 2 label, 3 memory, 4 face, 5 face_mask,
// 6 W1, 7 b1, 8 w2.  Output: alpha [B, M*S] then context [B, DF].
// ---------------------------------------------------------------------------
extern "C" void kernel_launch(void* const* d_in, const int* in_sizes, int n_in,
                              void* d_out, int out_size)
{
    const float* fc     = (const float*)d_in[0];
    const float* img    = (const float*)d_in[1];
    const float* label  = (const float*)d_in[2];
    const float* memory = (const float*)d_in[3];
    const float* face   = (const float*)d_in[4];
    const float* fmask  = (const float*)d_in[5];
    const float* W1     = (const float*)d_in[6];
    const float* b1     = (const float*)d_in[7];
    const float* w2     = (const float*)d_in[8];

    float* out   = (float*)d_out;
    float* alpha = out;                      // [B, M*S]
    float* ctx   = out + BB * MM * SS;       // [B, DF]

    cudaFuncSetAttribute(gemm_pb_mma, cudaFuncAttributeMaxDynamicSharedMemorySize, DYN_SMEM);

    convert_w_kernel<<<(W4 + 255) / 256, 256>>>(W1);
    pm_kernel<<<(BB * MM * HH) * 32 / 256, 256>>>(memory, label, W1, b1);
    gemm_pb_mma<<<dim3(HH / GN, (BB * SS) / GM), 512, DYN_SMEM>>>(face, fc, img, w2);
    softmax_kernel<<<BB, 1024>>>(fmask, alpha);
    context_kernel<<<BB, 512>>>(face, alpha, ctx);
}

// round 10
// speedup vs baseline: 1.1269x; 1.1269x over previous
#include <cuda_runtime.h>
#include <cuda_bf16.h>
#include <math_constants.h>
#include <cstdint>

// Problem constants
#define BB    32
#define SS    512
#define MM    8
#define HH    512
#define KBIG  1536          // face|fc|img (label folded into pm)
#define DIM1_ 2048
#define WCOLS 2560
#define EPSF  1e-5f

// GEMM tiling: CTA 128x256, warp tile 64x32, 16 warps (512 threads)
#define GM 128
#define GN 256
#define KC 64                        // bf16 k per chunk = 128 B/row
#define NCH (KBIG / KC)              // 24 chunks
#define A_TILE 16384                 // 128 rows x 128 B
#define B_TILE 32768                 // 256 rows x 128 B
#define STAGE_BYTES (2 * A_TILE + 2 * B_TILE)   // Ahi|Alo|Bhi|Blo = 96 KB
#define DYN_SMEM (2 * STAGE_BYTES + 1024)

// Scratch (device globals — no allocation allowed)
__device__ float g_pb[(size_t)BB * SS * HH];   // part_base [B*S, H]
__device__ float g_pm[BB * MM * HH];           // part_mem + label part + b1
__device__ float g_e [BB * MM * SS];           // logits e[b, m*S+s]
// Pre-converted bf16 hi/lo W1 slice
__device__ __nv_bfloat16 g_Whi[HH * KBIG];
__device__ __nv_bfloat16 g_Wlo[HH * KBIG];

__device__ __forceinline__ uint32_t smem_u32(const void* p) {
    return (uint32_t)__cvta_generic_to_shared(p);
}

#define LDMX4(r, addr) \
    asm volatile("ldmatrix.sync.aligned.m8n8.x4.shared.b16 {%0,%1,%2,%3}, [%4];" \
        : "=r"((r)[0]), "=r"((r)[1]), "=r"((r)[2]), "=r"((r)[3]) : "r"(addr))

#define MMA16816(d, a, b0v, b1v) \
    asm volatile("mma.sync.aligned.m16n8k16.row.col.f32.bf16.bf16.f32 " \
        "{%0,%1,%2,%3}, {%4,%5,%6,%7}, {%8,%9}, {%0,%1,%2,%3};" \
        : "+f"((d)[0]), "+f"((d)[1]), "+f"((d)[2]), "+f"((d)[3]) \
        : "r"((a)[0]), "r"((a)[1]), "r"((a)[2]), "r"((a)[3]), "r"(b0v), "r"(b1v))

#define CPASYNC(dst, src) \
    asm volatile("cp.async.cg.shared.global [%0], [%1], 16;" :: "r"(dst), "l"(src))
#define CPCOMMIT() asm volatile("cp.async.commit_group;" ::: "memory")
#define CPWAIT1()  asm volatile("cp.async.wait_group 1;" ::: "memory")

// 1-MUFU tanh (arch-agnostic PTX, sm_75+)
__device__ __forceinline__ float fast_tanh(float x) {
    float y;
    asm("tanh.approx.f32 %0, %1;" : "=f"(y) : "f"(x));
    return y;
}

// fp32x4 -> bf16 hi/lo pairs
__device__ __forceinline__ void cvt4(float4 v, uint2& hi, uint2& lo) {
    __nv_bfloat162 h0, h1, l0, l1;
    h0.x = __float2bfloat16_rn(v.x); h0.y = __float2bfloat16_rn(v.y);
    h1.x = __float2bfloat16_rn(v.z); h1.y = __float2bfloat16_rn(v.w);
    l0.x = __float2bfloat16_rn(v.x - __bfloat162float(h0.x));
    l0.y = __float2bfloat16_rn(v.y - __bfloat162float(h0.y));
    l1.x = __float2bfloat16_rn(v.z - __bfloat162float(h1.x));
    l1.y = __float2bfloat16_rn(v.w - __bfloat162float(h1.y));
    hi = make_uint2(*(uint32_t*)&h0, *(uint32_t*)&h1);
    lo = make_uint2(*(uint32_t*)&l0, *(uint32_t*)&l1);
}

// ---------------------------------------------------------------------------
// Kernel 0 (merged): blocks [0, NB_PM) compute pm; blocks [NB_PM, +NB_W) do
// the one-shot W1 fp32 -> bf16 hi/lo conversion.
// ---------------------------------------------------------------------------
#define W4    (HH * KBIG / 4)                // 196608 float4s
#define NB_PM ((BB * MM * HH) / 8)           // warp per pm output, 8 warps/blk
#define NB_W  ((W4 + 255) / 256)

__global__ __launch_bounds__(256)
void setup_kernel(const float* __restrict__ W1, const float* __restrict__ memory,
                  const float* __restrict__ label, const float* __restrict__ b1)
{
    const int tid = threadIdx.x;
    if (blockIdx.x < NB_PM) {
        const int gw   = (blockIdx.x * 256 + tid) >> 5;   // 0 .. B*M*H-1
        const int lane = tid & 31;
        const int h  = gw & (HH - 1);
        const int bm = gw >> 9;
        const int b  = bm >> 3;

        const float* __restrict__ wmem = W1 + (size_t)h * WCOLS + DIM1_;
        const float* __restrict__ wlab = W1 + (size_t)h * WCOLS + KBIG;
        const float* __restrict__ mrow = memory + (size_t)bm * HH;
        const float* __restrict__ lrow = label  + (size_t)b * 512;

        float acc = 0.f;
#pragma unroll 4
        for (int d = lane; d < HH; d += 32)
            acc = fmaf(wmem[d], mrow[d], fmaf(wlab[d], lrow[d], acc));
#pragma unroll
        for (int o = 16; o; o >>= 1) acc += __shfl_xor_sync(0xFFFFFFFFu, acc, o);
        if (lane == 0) g_pm[gw] = acc + b1[h];
    } else {
        const int idx = (blockIdx.x - NB_PM) * 256 + tid;
        if (idx >= W4) return;
        const int h = idx / (KBIG / 4);
        const int k = (idx % (KBIG / 4)) * 4;
        uint2 hi, lo;
        cvt4(*(const float4*)&W1[(size_t)h * WCOLS + k], hi, lo);
        *(uint2*)&g_Whi[h * KBIG + k] = hi;
        *(uint2*)&g_Wlo[h * KBIG + k] = lo;
    }
}

// ---------------------------------------------------------------------------
// GEMM (stage layout: Ahi 0 | Alo 16K | Bhi 32K | Blo 64K), 512 threads.
// A converted in-kernel inside the HMMA shadow; B (W1 hi/lo) via cp.async.
// ---------------------------------------------------------------------------
__device__ __forceinline__ void load_B(uint32_t sb, int tid, int colBase, int kt)
{
#pragma unroll
    for (int i = 0; i < 4; i++) {
        const int v   = tid + i * 512;
        const int row = v >> 3;
        const int cs  = v & 7;
        const uint32_t off = (uint32_t)row * 128 + cs * 16;
        const uint32_t sw  = off ^ ((off >> 3) & 0x70);
        const size_t boff = (size_t)(colBase + row) * KBIG + kt * KC + cs * 8;
        CPASYNC(sb + 2 * A_TILE + sw,          (const char*)&g_Whi[boff]);
        CPASYNC(sb + 2 * A_TILE + B_TILE + sw, (const char*)&g_Wlo[boff]);
    }
}

__device__ __forceinline__ void load_A(float4 (&av)[4], int tid, int rowBase, int kt,
        const float* __restrict__ face, const float* __restrict__ fc,
        const float* __restrict__ img)
{
    const int f = kt >> 3;
    const float* src = (f == 0) ? face : (f == 1 ? fc : img);
    const int row = rowBase + (tid >> 2);
    const int col = (kt & 7) * KC + (tid & 3) * 16;
    const float* p = &src[(size_t)row * 512 + col];
#pragma unroll
    for (int j = 0; j < 4; j++) av[j] = *(const float4*)(p + j * 4);
}

__device__ __forceinline__ void sts_A(uint32_t sb, int tid, const float4 (&av)[4])
{
    const uint32_t rowoff = (uint32_t)(tid >> 2) * 128 + (tid & 3) * 32;
#pragma unroll
    for (int j = 0; j < 4; j++) {
        uint2 hi, lo;
        cvt4(av[j], hi, lo);
        const uint32_t off = rowoff + j * 8;
        const uint32_t sw  = off ^ ((off >> 3) & 0x70);
        *(uint2*)(uintptr_t)__cvta_shared_to_generic(sb + sw)          = hi;
        *(uint2*)(uintptr_t)__cvta_shared_to_generic(sb + A_TILE + sw) = lo;
    }
}

__device__ __forceinline__ void mma_stage(uint32_t sb, float (&d)[4][4][4],
        int mw, int nw, int a_r, int a_kh, int b_r, int b_kh)
{
#pragma unroll
    for (int ks = 0; ks < 4; ks++) {
        const uint32_t kb = (uint32_t)(ks * 2) * 16;

        uint32_t ah[4][4];
#pragma unroll
        for (int i = 0; i < 4; i++) {
            const uint32_t off = (uint32_t)(mw * 64 + i * 16 + a_r) * 128 + kb + a_kh * 16;
            LDMX4(ah[i], sb + (off ^ ((off >> 3) & 0x70)));
        }
        uint32_t bh[2][4];
#pragma unroll
        for (int p = 0; p < 2; p++) {
            const uint32_t off = (uint32_t)(nw * 32 + p * 16 + b_r) * 128 + kb + b_kh * 16;
            LDMX4(bh[p], sb + 2 * A_TILE + (off ^ ((off >> 3) & 0x70)));
        }
#pragma unroll
        for (int i = 0; i < 4; i++)
#pragma unroll
            for (int p = 0; p < 2; p++) {
                MMA16816(d[i][2 * p],     ah[i], bh[p][0], bh[p][1]);
                MMA16816(d[i][2 * p + 1], ah[i], bh[p][2], bh[p][3]);
            }
        {
            uint32_t bl[2][4];
#pragma unroll
            for (int p = 0; p < 2; p++) {
                const uint32_t off = (uint32_t)(nw * 32 + p * 16 + b_r) * 128 + kb + b_kh * 16;
                LDMX4(bl[p], sb + 2 * A_TILE + B_TILE + (off ^ ((off >> 3) & 0x70)));
            }
#pragma unroll
            for (int i = 0; i < 4; i++)
#pragma unroll
                for (int p = 0; p < 2; p++) {
                    MMA16816(d[i][2 * p],     ah[i], bl[p][0], bl[p][1]);
                    MMA16816(d[i][2 * p + 1], ah[i], bl[p][2], bl[p][3]);
                }
        }
        {
            uint32_t al[4][4];
#pragma unroll
            for (int i = 0; i < 4; i++) {
                const uint32_t off = (uint32_t)(mw * 64 + i * 16 + a_r) * 128 + kb + a_kh * 16;
                LDMX4(al[i], sb + A_TILE + (off ^ ((off >> 3) & 0x70)));
            }
#pragma unroll
            for (int i = 0; i < 4; i++)
#pragma unroll
                for (int p = 0; p < 2; p++) {
                    MMA16816(d[i][2 * p],     al[i], bh[p][0], bh[p][1]);
                    MMA16816(d[i][2 * p + 1], al[i], bh[p][2], bh[p][3]);
                }
        }
    }
}

__global__ __launch_bounds__(512, 1)
void gemm_pb_mma(const float* __restrict__ face, const float* __restrict__ fc,
                 const float* __restrict__ img)
{
    extern __shared__ char dynsmem[];
    const uint32_t dynaddr = smem_u32(dynsmem);
    const uint32_t sbase = (dynaddr + 1023) & ~1023u;

    const int tid  = threadIdx.x;
    const int warp = tid >> 5;
    const int lane = tid & 31;
    const int mw = warp >> 3;            // 0..1 : m offset mw*64
    const int nw = warp & 7;             // 0..7 : n offset nw*32
    const int colBase = blockIdx.x * GN;
    const int rowBase = blockIdx.y * GM;

    const int a_r  = lane & 15;
    const int a_kh = lane >> 4;
    const int b_r  = (lane & 7) + ((lane >> 4) << 3);
    const int b_kh = (lane >> 3) & 1;

    float d[4][4][4];
#pragma unroll
    for (int i = 0; i < 4; i++)
#pragma unroll
        for (int j = 0; j < 4; j++)
#pragma unroll
            for (int q = 0; q < 4; q++) d[i][j][q] = 0.f;

    float4 av[4];
    load_A(av, tid, rowBase, 0, face, fc, img);
    load_B(sbase, tid, colBase, 0);
    CPCOMMIT();
    load_B(sbase + STAGE_BYTES, tid, colBase, 1);
    CPCOMMIT();
    sts_A(sbase, tid, av);
    load_A(av, tid, rowBase, 1, face, fc, img);

    for (int kt = 0; kt < NCH; kt++) {
        CPWAIT1();
        __syncthreads();
        if (kt + 1 < NCH) sts_A(sbase + ((kt + 1) & 1) * STAGE_BYTES, tid, av);
        if (kt + 2 < NCH) load_A(av, tid, rowBase, kt + 2, face, fc, img);
        mma_stage(sbase + (kt & 1) * STAGE_BYTES, d, mw, nw, a_r, a_kh, b_r, b_kh);
        __syncthreads();
        if (kt + 2 < NCH) load_B(sbase + (kt & 1) * STAGE_BYTES, tid, colBase, kt + 2);
        CPCOMMIT();
    }

    // Epilogue: fragment layout -> g_pb
    const int r0 = rowBase + mw * 64 + (lane >> 2);
    const int c0 = colBase + nw * 32 + (lane & 3) * 2;
#pragma unroll
    for (int i = 0; i < 4; i++)
#pragma unroll
        for (int nt = 0; nt < 4; nt++) {
            const int row = r0 + i * 16;
            const int col = c0 + nt * 8;
            *(float2*)&g_pb[(size_t)row * HH + col]       = make_float2(d[i][nt][0], d[i][nt][1]);
            *(float2*)&g_pb[(size_t)(row + 8) * HH + col] = make_float2(d[i][nt][2], d[i][nt][3]);
        }
}

// ---------------------------------------------------------------------------
// Kernel 3: e[b, m*S+s] = sum_h w2[h] * tanh(pb[b,s,h] + pm[b,m,h]).
// Warp per s; ALL 16 pb values front-batched into registers (MLP 16).
// ---------------------------------------------------------------------------
__global__ __launch_bounds__(256)
void e_kernel(const float* __restrict__ w2)
{
    __shared__ float pm_s[MM][HH];
    __shared__ float w2_s[HH];

    const int b   = blockIdx.y;
    const int tid = threadIdx.x;
    for (int i = tid; i < MM * HH; i += 256) ((float*)pm_s)[i] = g_pm[b * MM * HH + i];
    for (int i = tid; i < HH; i += 256)      w2_s[i] = w2[i];
    __syncthreads();

    const int warp = tid >> 5, lane = tid & 31;
    const int s = blockIdx.x * 8 + warp;
    const float* __restrict__ pb = g_pb + (size_t)(b * SS + s) * HH;

    float pv[16];
#pragma unroll
    for (int j = 0; j < 16; j++) pv[j] = pb[lane + j * 32];

    float acc[MM];
#pragma unroll
    for (int m = 0; m < MM; m++) acc[m] = 0.f;

#pragma unroll
    for (int j = 0; j < 16; j++) {
        const int h = lane + j * 32;
        const float w2v = w2_s[h];
#pragma unroll
        for (int m = 0; m < MM; m++)
            acc[m] = fmaf(w2v, fast_tanh(pv[j] + pm_s[m][h]), acc[m]);
    }
#pragma unroll
    for (int m = 0; m < MM; m++)
#pragma unroll
        for (int o = 16; o; o >>= 1) acc[m] += __shfl_xor_sync(0xFFFFFFFFu, acc[m], o);

    if (lane == 0) {
#pragma unroll
        for (int m = 0; m < MM; m++) g_e[b * MM * SS + m * SS + s] = acc[m];
    }
}

// ---------------------------------------------------------------------------
// Kernel 4: softmax over 4096, *mask, renorm by (masked_sum + EPS), PLUS the
// fused context: ctx[b,d] = sum_s (sum_m alpha[b,m,s]) * face[b,s,d].
// ---------------------------------------------------------------------------
__global__ __launch_bounds__(1024)
void softmax_ctx_kernel(const float* __restrict__ face_mask,
                        const float* __restrict__ face,
                        float* __restrict__ alpha, float* __restrict__ ctx)
{
    __shared__ float sred[32];
    __shared__ float asum[1024];     // per-s partials then folded [0..511]
    __shared__ float csum[512];
    const int b = blockIdx.x;
    const int tid = threadIdx.x;
    const int w = tid >> 5, l = tid & 31;
    const float* __restrict__ e = g_e + b * (MM * SS);

    float v[4];
    float mx = -CUDART_INF_F;
#pragma unroll
    for (int i = 0; i < 4; i++) { v[i] = e[tid + i * 1024]; mx = fmaxf(mx, v[i]); }

#pragma unroll
    for (int o = 16; o; o >>= 1) mx = fmaxf(mx, __shfl_xor_sync(0xFFFFFFFFu, mx, o));
    if (l == 0) sred[w] = mx;
    __syncthreads();
    if (tid < 32) {
        float t = sred[tid];
#pragma unroll
        for (int o = 16; o; o >>= 1) t = fmaxf(t, __shfl_xor_sync(0xFFFFFFFFu, t, o));
        if (tid == 0) sred[0] = t;
    }
    __syncthreads();
    mx = sred[0];
    __syncthreads();

    float sum = 0.f;
#pragma unroll
    for (int i = 0; i < 4; i++) { v[i] = __expf(v[i] - mx); sum += v[i]; }
#pragma unroll
    for (int o = 16; o; o >>= 1) sum += __shfl_xor_sync(0xFFFFFFFFu, sum, o);
    if (l == 0) sred[w] = sum;
    __syncthreads();
    if (tid < 32) {
        float t = sred[tid];
#pragma unroll
        for (int o = 16; o; o >>= 1) t += __shfl_xor_sync(0xFFFFFFFFu, t, o);
        if (tid == 0) sred[0] = t;
    }
    __syncthreads();
    const float Z = sred[0];
    __syncthreads();

    const float invZ = 1.f / Z;
    float msum = 0.f;
#pragma unroll
    for (int i = 0; i < 4; i++) {
        const int idx = tid + i * 1024;
        const float mk = face_mask[b * SS + (idx & 511)];
        v[i] = v[i] * invZ * mk;
        msum += v[i];
    }
#pragma unroll
    for (int o = 16; o; o >>= 1) msum += __shfl_xor_sync(0xFFFFFFFFu, msum, o);
    if (l == 0) sred[w] = msum;
    __syncthreads();
    if (tid < 32) {
        float t = sred[tid];
#pragma unroll
        for (int o = 16; o; o >>= 1) t += __shfl_xor_sync(0xFFFFFFFFu, t, o);
        if (tid == 0) sred[0] = t;
    }
    __syncthreads();
    const float inv = 1.f / (sred[0] + EPSF);

    // alpha write + per-s m-partials (thread tid holds m ∈ {0,2,4,6} or
    // {1,3,5,7} for s = tid & 511, i.e. idx = tid + i*1024 → m = idx>>9).
    float part = 0.f;
#pragma unroll
    for (int i = 0; i < 4; i++) {
        const float a = v[i] * inv;
        alpha[b * (MM * SS) + tid + i * 1024] = a;
        part += a;
    }
    asum[tid] = part;
    __syncthreads();
    if (tid < 512) asum[tid] += asum[tid + 512];   // asum[s] = sum_m alpha
    __syncthreads();

    // context: d = tid & 511, s-half = tid >> 9
    const int dcol = tid & 511;
    const int sh   = tid >> 9;
    const float* __restrict__ fb = face + (size_t)b * SS * 512 + (size_t)sh * 256 * 512;
    const float* __restrict__ as = asum + sh * 256;
    float c0 = 0.f, c1 = 0.f;
#pragma unroll 4
    for (int s = 0; s < 256; s += 2) {
        c0 = fmaf(as[s],     fb[(size_t)s * 512 + dcol],      c0);
        c1 = fmaf(as[s + 1], fb[(size_t)(s + 1) * 512 + dcol], c1);
    }
    if (sh == 0) csum[dcol] = c0 + c1;
    __syncthreads();
    if (sh == 1) ctx[b * 512 + dcol] = csum[dcol] + c0 + c1;
}

// ---------------------------------------------------------------------------
// Launch. Inputs: 0 fc, 1 img, 2 label, 3 memory, 4 face, 5 face_mask,
// 6 W1, 7 b1, 8 w2.  Output: alpha [B, M*S] then context [B, DF].
// ---------------------------------------------------------------------------
extern "C" void kernel_launch(void* const* d_in, const int* in_sizes, int n_in,
                              void* d_out, int out_size)
{
    const float* fc     = (const float*)d_in[0];
    const float* img    = (const float*)d_in[1];
    const float* label  = (const float*)d_in[2];
    const float* memory = (const float*)d_in[3];
    const float* face   = (const float*)d_in[4];
    const float* fmask  = (const float*)d_in[5];
    const float* W1     = (const float*)d_in[6];
    const float* b1     = (const float*)d_in[7];
    const float* w2     = (const float*)d_in[8];

    float* out   = (float*)d_out;
    float* alpha = out;                      // [B, M*S]
    float* ctx   = out + BB * MM * SS;       // [B, DF]

    cudaFuncSetAttribute(gemm_pb_mma, cudaFuncAttributeMaxDynamicSharedMemorySize, DYN_SMEM);

    setup_kernel<<<NB_PM + NB_W, 256>>>(W1, memory, label, b1);
    gemm_pb_mma<<<dim3(HH / GN, (BB * SS) / GM), 512, DYN_SMEM>>>(face, fc, img);
    e_kernel<<<dim3(SS / 8, BB), 256>>>(w2);
    softmax_ctx_kernel<<<BB, 1024>>>(fmask, face, alpha, ctx);
}

// round 11
// speedup vs baseline: 1.1541x; 1.0242x over previous
#include <cuda_runtime.h>
#include <cuda_bf16.h>
#include <math_constants.h>
#include <cstdint>

// Problem constants
#define BB    32
#define SS    512
#define MM    8
#define HH    512
#define KBIG  1536          // face|fc|img (label folded into pm)
#define DIM1_ 2048
#define WCOLS 2560
#define EPSF  1e-5f

// GEMM tiling: CTA 128x256, warp tile 64x32, 16 warps (512 threads)
#define GM 128
#define GN 256
#define KC 64                        // bf16 k per chunk = 128 B/row
#define NCH (KBIG / KC)              // 24 chunks
#define A_TILE 16384                 // 128 rows x 128 B
#define B_TILE 32768                 // 256 rows x 128 B
#define STAGE_BYTES (2 * A_TILE + 2 * B_TILE)   // Ahi|Alo|Bhi|Blo = 96 KB
#define DYN_SMEM (2 * STAGE_BYTES + 1024)

// Scratch (device globals — no allocation allowed)
__device__ float g_pb[(size_t)BB * SS * HH];   // part_base [B*S, H]
__device__ float g_pm[BB * MM * HH];           // part_mem + label part + b1
__device__ float g_e [BB * MM * SS];           // logits e[b, m*S+s]
__device__ float g_as[BB * SS];                // per-s alpha sums (over m)
__device__ float g_cp[BB * 4 * 512];           // context partials (4 s-quarters)
// Pre-converted bf16 hi/lo W1 slice
__device__ __nv_bfloat16 g_Whi[HH * KBIG];
__device__ __nv_bfloat16 g_Wlo[HH * KBIG];

__device__ __forceinline__ uint32_t smem_u32(const void* p) {
    return (uint32_t)__cvta_generic_to_shared(p);
}

#define LDMX4(r, addr) \
    asm volatile("ldmatrix.sync.aligned.m8n8.x4.shared.b16 {%0,%1,%2,%3}, [%4];" \
        : "=r"((r)[0]), "=r"((r)[1]), "=r"((r)[2]), "=r"((r)[3]) : "r"(addr))

#define MMA16816(d, a, b0v, b1v) \
    asm volatile("mma.sync.aligned.m16n8k16.row.col.f32.bf16.bf16.f32 " \
        "{%0,%1,%2,%3}, {%4,%5,%6,%7}, {%8,%9}, {%0,%1,%2,%3};" \
        : "+f"((d)[0]), "+f"((d)[1]), "+f"((d)[2]), "+f"((d)[3]) \
        : "r"((a)[0]), "r"((a)[1]), "r"((a)[2]), "r"((a)[3]), "r"(b0v), "r"(b1v))

#define CPASYNC(dst, src) \
    asm volatile("cp.async.cg.shared.global [%0], [%1], 16;" :: "r"(dst), "l"(src))
#define CPCOMMIT() asm volatile("cp.async.commit_group;" ::: "memory")
#define CPWAIT1()  asm volatile("cp.async.wait_group 1;" ::: "memory")

// 1-MUFU tanh (arch-agnostic PTX, sm_75+)
__device__ __forceinline__ float fast_tanh(float x) {
    float y;
    asm("tanh.approx.f32 %0, %1;" : "=f"(y) : "f"(x));
    return y;
}

// fp32x4 -> bf16 hi/lo pairs
__device__ __forceinline__ void cvt4(float4 v, uint2& hi, uint2& lo) {
    __nv_bfloat162 h0, h1, l0, l1;
    h0.x = __float2bfloat16_rn(v.x); h0.y = __float2bfloat16_rn(v.y);
    h1.x = __float2bfloat16_rn(v.z); h1.y = __float2bfloat16_rn(v.w);
    l0.x = __float2bfloat16_rn(v.x - __bfloat162float(h0.x));
    l0.y = __float2bfloat16_rn(v.y - __bfloat162float(h0.y));
    l1.x = __float2bfloat16_rn(v.z - __bfloat162float(h1.x));
    l1.y = __float2bfloat16_rn(v.w - __bfloat162float(h1.y));
    hi = make_uint2(*(uint32_t*)&h0, *(uint32_t*)&h1);
    lo = make_uint2(*(uint32_t*)&l0, *(uint32_t*)&l1);
}

// ---------------------------------------------------------------------------
// Kernel 0 (merged): blocks [0, NB_PM) compute pm; blocks [NB_PM, +NB_W) do
// the one-shot W1 fp32 -> bf16 hi/lo conversion.
// ---------------------------------------------------------------------------
#define W4    (HH * KBIG / 4)                // 196608 float4s
#define NB_PM ((BB * MM * HH) / 8)           // warp per pm output, 8 warps/blk
#define NB_W  ((W4 + 255) / 256)

__global__ __launch_bounds__(256)
void setup_kernel(const float* __restrict__ W1, const float* __restrict__ memory,
                  const float* __restrict__ label, const float* __restrict__ b1)
{
    const int tid = threadIdx.x;
    if (blockIdx.x < NB_PM) {
        const int gw   = (blockIdx.x * 256 + tid) >> 5;   // 0 .. B*M*H-1
        const int lane = tid & 31;
        const int h  = gw & (HH - 1);
        const int bm = gw >> 9;
        const int b  = bm >> 3;

        const float* __restrict__ wmem = W1 + (size_t)h * WCOLS + DIM1_;
        const float* __restrict__ wlab = W1 + (size_t)h * WCOLS + KBIG;
        const float* __restrict__ mrow = memory + (size_t)bm * HH;
        const float* __restrict__ lrow = label  + (size_t)b * 512;

        float acc = 0.f;
#pragma unroll 4
        for (int d = lane; d < HH; d += 32)
            acc = fmaf(wmem[d], mrow[d], fmaf(wlab[d], lrow[d], acc));
#pragma unroll
        for (int o = 16; o; o >>= 1) acc += __shfl_xor_sync(0xFFFFFFFFu, acc, o);
        if (lane == 0) g_pm[gw] = acc + b1[h];
    } else {
        const int idx = (blockIdx.x - NB_PM) * 256 + tid;
        if (idx >= W4) return;
        const int h = idx / (KBIG / 4);
        const int k = (idx % (KBIG / 4)) * 4;
        uint2 hi, lo;
        cvt4(*(const float4*)&W1[(size_t)h * WCOLS + k], hi, lo);
        *(uint2*)&g_Whi[h * KBIG + k] = hi;
        *(uint2*)&g_Wlo[h * KBIG + k] = lo;
    }
}

// ---------------------------------------------------------------------------
// GEMM (stage layout: Ahi 0 | Alo 16K | Bhi 32K | Blo 64K), 512 threads.
// A converted in-kernel inside the HMMA shadow; B (W1 hi/lo) via cp.async.
// ---------------------------------------------------------------------------
__device__ __forceinline__ void load_B(uint32_t sb, int tid, int colBase, int kt)
{
#pragma unroll
    for (int i = 0; i < 4; i++) {
        const int v   = tid + i * 512;
        const int row = v >> 3;
        const int cs  = v & 7;
        const uint32_t off = (uint32_t)row * 128 + cs * 16;
        const uint32_t sw  = off ^ ((off >> 3) & 0x70);
        const size_t boff = (size_t)(colBase + row) * KBIG + kt * KC + cs * 8;
        CPASYNC(sb + 2 * A_TILE + sw,          (const char*)&g_Whi[boff]);
        CPASYNC(sb + 2 * A_TILE + B_TILE + sw, (const char*)&g_Wlo[boff]);
    }
}

__device__ __forceinline__ void load_A(float4 (&av)[4], int tid, int rowBase, int kt,
        const float* __restrict__ face, const float* __restrict__ fc,
        const float* __restrict__ img)
{
    const int f = kt >> 3;
    const float* src = (f == 0) ? face : (f == 1 ? fc : img);
    const int row = rowBase + (tid >> 2);
    const int col = (kt & 7) * KC + (tid & 3) * 16;
    const float* p = &src[(size_t)row * 512 + col];
#pragma unroll
    for (int j = 0; j < 4; j++) av[j] = *(const float4*)(p + j * 4);
}

__device__ __forceinline__ void sts_A(uint32_t sb, int tid, const float4 (&av)[4])
{
    const uint32_t rowoff = (uint32_t)(tid >> 2) * 128 + (tid & 3) * 32;
#pragma unroll
    for (int j = 0; j < 4; j++) {
        uint2 hi, lo;
        cvt4(av[j], hi, lo);
        const uint32_t off = rowoff + j * 8;
        const uint32_t sw  = off ^ ((off >> 3) & 0x70);
        *(uint2*)(uintptr_t)__cvta_shared_to_generic(sb + sw)          = hi;
        *(uint2*)(uintptr_t)__cvta_shared_to_generic(sb + A_TILE + sw) = lo;
    }
}

__device__ __forceinline__ void mma_stage(uint32_t sb, float (&d)[4][4][4],
        int mw, int nw, int a_r, int a_kh, int b_r, int b_kh)
{
#pragma unroll
    for (int ks = 0; ks < 4; ks++) {
        const uint32_t kb = (uint32_t)(ks * 2) * 16;

        uint32_t ah[4][4];
#pragma unroll
        for (int i = 0; i < 4; i++) {
            const uint32_t off = (uint32_t)(mw * 64 + i * 16 + a_r) * 128 + kb + a_kh * 16;
            LDMX4(ah[i], sb + (off ^ ((off >> 3) & 0x70)));
        }
        uint32_t bh[2][4];
#pragma unroll
        for (int p = 0; p < 2; p++) {
            const uint32_t off = (uint32_t)(nw * 32 + p * 16 + b_r) * 128 + kb + b_kh * 16;
            LDMX4(bh[p], sb + 2 * A_TILE + (off ^ ((off >> 3) & 0x70)));
        }
#pragma unroll
        for (int i = 0; i < 4; i++)
#pragma unroll
            for (int p = 0; p < 2; p++) {
                MMA16816(d[i][2 * p],     ah[i], bh[p][0], bh[p][1]);
                MMA16816(d[i][2 * p + 1], ah[i], bh[p][2], bh[p][3]);
            }
        {
            uint32_t bl[2][4];
#pragma unroll
            for (int p = 0; p < 2; p++) {
                const uint32_t off = (uint32_t)(nw * 32 + p * 16 + b_r) * 128 + kb + b_kh * 16;
                LDMX4(bl[p], sb + 2 * A_TILE + B_TILE + (off ^ ((off >> 3) & 0x70)));
            }
#pragma unroll
            for (int i = 0; i < 4; i++)
#pragma unroll
                for (int p = 0; p < 2; p++) {
                    MMA16816(d[i][2 * p],     ah[i], bl[p][0], bl[p][1]);
                    MMA16816(d[i][2 * p + 1], ah[i], bl[p][2], bl[p][3]);
                }
        }
        {
            uint32_t al[4][4];
#pragma unroll
            for (int i = 0; i < 4; i++) {
                const uint32_t off = (uint32_t)(mw * 64 + i * 16 + a_r) * 128 + kb + a_kh * 16;
                LDMX4(al[i], sb + A_TILE + (off ^ ((off >> 3) & 0x70)));
            }
#pragma unroll
            for (int i = 0; i < 4; i++)
#pragma unroll
                for (int p = 0; p < 2; p++) {
                    MMA16816(d[i][2 * p],     al[i], bh[p][0], bh[p][1]);
                    MMA16816(d[i][2 * p + 1], al[i], bh[p][2], bh[p][3]);
                }
        }
    }
}

__global__ __launch_bounds__(512, 1)
void gemm_pb_mma(const float* __restrict__ face, const float* __restrict__ fc,
                 const float* __restrict__ img)
{
    extern __shared__ char dynsmem[];
    const uint32_t dynaddr = smem_u32(dynsmem);
    const uint32_t sbase = (dynaddr + 1023) & ~1023u;

    const int tid  = threadIdx.x;
    const int warp = tid >> 5;
    const int lane = tid & 31;
    const int mw = warp >> 3;            // 0..1 : m offset mw*64
    const int nw = warp & 7;             // 0..7 : n offset nw*32
    const int colBase = blockIdx.x * GN;
    const int rowBase = blockIdx.y * GM;

    const int a_r  = lane & 15;
    const int a_kh = lane >> 4;
    const int b_r  = (lane & 7) + ((lane >> 4) << 3);
    const int b_kh = (lane >> 3) & 1;

    float d[4][4][4];
#pragma unroll
    for (int i = 0; i < 4; i++)
#pragma unroll
        for (int j = 0; j < 4; j++)
#pragma unroll
            for (int q = 0; q < 4; q++) d[i][j][q] = 0.f;

    float4 av[4];
    load_A(av, tid, rowBase, 0, face, fc, img);
    load_B(sbase, tid, colBase, 0);
    CPCOMMIT();
    load_B(sbase + STAGE_BYTES, tid, colBase, 1);
    CPCOMMIT();
    sts_A(sbase, tid, av);
    load_A(av, tid, rowBase, 1, face, fc, img);

    for (int kt = 0; kt < NCH; kt++) {
        CPWAIT1();
        __syncthreads();
        if (kt + 1 < NCH) sts_A(sbase + ((kt + 1) & 1) * STAGE_BYTES, tid, av);
        if (kt + 2 < NCH) load_A(av, tid, rowBase, kt + 2, face, fc, img);
        mma_stage(sbase + (kt & 1) * STAGE_BYTES, d, mw, nw, a_r, a_kh, b_r, b_kh);
        __syncthreads();
        if (kt + 2 < NCH) load_B(sbase + (kt & 1) * STAGE_BYTES, tid, colBase, kt + 2);
        CPCOMMIT();
    }

    // Epilogue: fragment layout -> g_pb
    const int r0 = rowBase + mw * 64 + (lane >> 2);
    const int c0 = colBase + nw * 32 + (lane & 3) * 2;
#pragma unroll
    for (int i = 0; i < 4; i++)
#pragma unroll
        for (int nt = 0; nt < 4; nt++) {
            const int row = r0 + i * 16;
            const int col = c0 + nt * 8;
            *(float2*)&g_pb[(size_t)row * HH + col]       = make_float2(d[i][nt][0], d[i][nt][1]);
            *(float2*)&g_pb[(size_t)(row + 8) * HH + col] = make_float2(d[i][nt][2], d[i][nt][3]);
        }
}

// ---------------------------------------------------------------------------
// Kernel 3: e[b, m*S+s] = sum_h w2[h] * tanh(pb[b,s,h] + pm[b,m,h]).
// Warp per s; ALL 16 pb values front-batched into registers (MLP 16).
// ---------------------------------------------------------------------------
__global__ __launch_bounds__(256)
void e_kernel(const float* __restrict__ w2)
{
    __shared__ float pm_s[MM][HH];
    __shared__ float w2_s[HH];

    const int b   = blockIdx.y;
    const int tid = threadIdx.x;
    for (int i = tid; i < MM * HH; i += 256) ((float*)pm_s)[i] = g_pm[b * MM * HH + i];
    for (int i = tid; i < HH; i += 256)      w2_s[i] = w2[i];
    __syncthreads();

    const int warp = tid >> 5, lane = tid & 31;
    const int s = blockIdx.x * 8 + warp;
    const float* __restrict__ pb = g_pb + (size_t)(b * SS + s) * HH;

    float pv[16];
#pragma unroll
    for (int j = 0; j < 16; j++) pv[j] = pb[lane + j * 32];

    float acc[MM];
#pragma unroll
    for (int m = 0; m < MM; m++) acc[m] = 0.f;

#pragma unroll
    for (int j = 0; j < 16; j++) {
        const int h = lane + j * 32;
        const float w2v = w2_s[h];
#pragma unroll
        for (int m = 0; m < MM; m++)
            acc[m] = fmaf(w2v, fast_tanh(pv[j] + pm_s[m][h]), acc[m]);
    }
#pragma unroll
    for (int m = 0; m < MM; m++)
#pragma unroll
        for (int o = 16; o; o >>= 1) acc[m] += __shfl_xor_sync(0xFFFFFFFFu, acc[m], o);

    if (lane == 0) {
#pragma unroll
        for (int m = 0; m < MM; m++) g_e[b * MM * SS + m * SS + s] = acc[m];
    }
}

// ---------------------------------------------------------------------------
// Kernel 4: softmax over 4096, *mask, renorm by (masked_sum + EPS).
// Also writes g_as[b][s] = sum_m alpha[b,m,s] for the context kernels.
// ---------------------------------------------------------------------------
__global__ __launch_bounds__(1024)
void softmax_kernel(const float* __restrict__ face_mask, float* __restrict__ alpha)
{
    __shared__ float sred[32];
    __shared__ float asum[1024];
    const int b = blockIdx.x;
    const int tid = threadIdx.x;
    const int w = tid >> 5, l = tid & 31;
    const float* __restrict__ e = g_e + b * (MM * SS);

    float v[4];
    float mx = -CUDART_INF_F;
#pragma unroll
    for (int i = 0; i < 4; i++) { v[i] = e[tid + i * 1024]; mx = fmaxf(mx, v[i]); }

#pragma unroll
    for (int o = 16; o; o >>= 1) mx = fmaxf(mx, __shfl_xor_sync(0xFFFFFFFFu, mx, o));
    if (l == 0) sred[w] = mx;
    __syncthreads();
    if (tid < 32) {
        float t = sred[tid];
#pragma unroll
        for (int o = 16; o; o >>= 1) t = fmaxf(t, __shfl_xor_sync(0xFFFFFFFFu, t, o));
        if (tid == 0) sred[0] = t;
    }
    __syncthreads();
    mx = sred[0];
    __syncthreads();

    float sum = 0.f;
#pragma unroll
    for (int i = 0; i < 4; i++) { v[i] = __expf(v[i] - mx); sum += v[i]; }
#pragma unroll
    for (int o = 16; o; o >>= 1) sum += __shfl_xor_sync(0xFFFFFFFFu, sum, o);
    if (l == 0) sred[w] = sum;
    __syncthreads();
    if (tid < 32) {
        float t = sred[tid];
#pragma unroll
        for (int o = 16; o; o >>= 1) t += __shfl_xor_sync(0xFFFFFFFFu, t, o);
        if (tid == 0) sred[0] = t;
    }
    __syncthreads();
    const float Z = sred[0];
    __syncthreads();

    const float invZ = 1.f / Z;
    float msum = 0.f;
#pragma unroll
    for (int i = 0; i < 4; i++) {
        const int idx = tid + i * 1024;
        const float mk = face_mask[b * SS + (idx & 511)];
        v[i] = v[i] * invZ * mk;
        msum += v[i];
    }
#pragma unroll
    for (int o = 16; o; o >>= 1) msum += __shfl_xor_sync(0xFFFFFFFFu, msum, o);
    if (l == 0) sred[w] = msum;
    __syncthreads();
    if (tid < 32) {
        float t = sred[tid];
#pragma unroll
        for (int o = 16; o; o >>= 1) t += __shfl_xor_sync(0xFFFFFFFFu, t, o);
        if (tid == 0) sred[0] = t;
    }
    __syncthreads();
    const float inv = 1.f / (sred[0] + EPSF);

    float part = 0.f;
#pragma unroll
    for (int i = 0; i < 4; i++) {
        const float a = v[i] * inv;
        alpha[b * (MM * SS) + tid + i * 1024] = a;
        part += a;
    }
    asum[tid] = part;
    __syncthreads();
    if (tid < 512) g_as[b * SS + tid] = asum[tid] + asum[tid + 512];
}

// ---------------------------------------------------------------------------
// Kernel 5a: context partials. Grid (4, B): block q reduces s in
// [q*128, q*128+128). 128 CTAs stream face in parallel.
// ---------------------------------------------------------------------------
__global__ __launch_bounds__(512)
void ctx_partial_kernel(const float* __restrict__ face)
{
    __shared__ float as_s[128];
    const int q = blockIdx.x;
    const int b = blockIdx.y;
    const int tid = threadIdx.x;

    if (tid < 128) as_s[tid] = g_as[b * SS + q * 128 + tid];
    __syncthreads();

    const float* __restrict__ fb = face + (size_t)b * SS * 512 + (size_t)q * 128 * 512;
    float c0 = 0.f, c1 = 0.f, c2 = 0.f, c3 = 0.f;
#pragma unroll 4
    for (int s = 0; s < 128; s += 4) {
        c0 = fmaf(as_s[s],     fb[(size_t)s * 512 + tid],       c0);
        c1 = fmaf(as_s[s + 1], fb[(size_t)(s + 1) * 512 + tid], c1);
        c2 = fmaf(as_s[s + 2], fb[(size_t)(s + 2) * 512 + tid], c2);
        c3 = fmaf(as_s[s + 3], fb[(size_t)(s + 3) * 512 + tid], c3);
    }
    g_cp[(b * 4 + q) * 512 + tid] = (c0 + c1) + (c2 + c3);
}

// ---------------------------------------------------------------------------
// Kernel 5b: sum the 4 partials -> ctx.
// ---------------------------------------------------------------------------
__global__ __launch_bounds__(512)
void ctx_reduce_kernel(float* __restrict__ ctx)
{
    const int b = blockIdx.x;
    const int tid = threadIdx.x;
    const float* __restrict__ p = &g_cp[b * 4 * 512 + tid];
    ctx[b * 512 + tid] = (p[0] + p[512]) + (p[1024] + p[1536]);
}

// ---------------------------------------------------------------------------
// Launch. Inputs: 0 fc, 1 img, 2 label, 3 memory, 4 face, 5 face_mask,
// 6 W1, 7 b1, 8 w2.  Output: alpha [B, M*S] then context [B, DF].
// ---------------------------------------------------------------------------
extern "C" void kernel_launch(void* const* d_in, const int* in_sizes, int n_in,
                              void* d_out, int out_size)
{
    const float* fc     = (const float*)d_in[0];
    const float* img    = (const float*)d_in[1];
    const float* label  = (const float*)d_in[2];
    const float* memory = (const float*)d_in[3];
    const float* face   = (const float*)d_in[4];
    const float* fmask  = (const float*)d_in[5];
    const float* W1     = (const float*)d_in[6];
    const float* b1     = (const float*)d_in[7];
    const float* w2     = (const float*)d_in[8];

    float* out   = (float*)d_out;
    float* alpha = out;                      // [B, M*S]
    float* ctx   = out + BB * MM * SS;       // [B, DF]

    cudaFuncSetAttribute(gemm_pb_mma, cudaFuncAttributeMaxDynamicSharedMemorySize, DYN_SMEM);

    setup_kernel<<<NB_PM + NB_W, 256>>>(W1, memory, label, b1);
    gemm_pb_mma<<<dim3(HH / GN, (BB * SS) / GM), 512, DYN_SMEM>>>(face, fc, img);
    e_kernel<<<dim3(SS / 8, BB), 256>>>(w2);
    softmax_kernel<<<BB, 1024>>>(fmask, alpha);
    ctx_partial_kernel<<<dim3(4, BB), 512>>>(face);
    ctx_reduce_kernel<<<BB, 512>>>(ctx);
}

// round 12
// speedup vs baseline: 1.3853x; 1.2003x over previous
#include <cuda_runtime.h>
#include <cuda_fp16.h>
#include <math_constants.h>
#include <cstdint>

// Problem constants
#define BB    32
#define SS    512
#define MM    8
#define HH    512
#define KBIG  1536          // face|fc|img (label folded into pm)
#define DIM1_ 2048
#define WCOLS 2560
#define EPSF  1e-5f

// GEMM tiling: CTA 128x256, warp tile 64x32, 16 warps (512 threads)
#define GM 128
#define GN 256
#define KC 64                        // fp16 k per chunk = 128 B/row
#define NCH (KBIG / KC)              // 24 chunks
#define A_TILE 16384                 // 128 rows x 128 B
#define B_TILE 32768                 // 256 rows x 128 B
#define STAGE_BYTES (2 * A_TILE + B_TILE)   // Ahi|Alo|W = 64 KB
#define DYN_SMEM (2 * STAGE_BYTES + 1024)

// Scratch (device globals — no allocation allowed)
__device__ float g_pb[(size_t)BB * SS * HH];   // part_base [B*S, H]
__device__ float g_pm[BB * MM * HH];           // part_mem + label part + b1
__device__ float g_e [BB * MM * SS];           // logits e[b, m*S+s]
__device__ float g_as[BB * SS];                // per-s alpha sums (over m)
__device__ float g_cp[BB * 4 * 512];           // context partials
__device__ __half g_W16[HH * KBIG];            // W1 slice, fp16

__device__ __forceinline__ uint32_t smem_u32(const void* p) {
    return (uint32_t)__cvta_generic_to_shared(p);
}

#define LDMX4(r, addr) \
    asm volatile("ldmatrix.sync.aligned.m8n8.x4.shared.b16 {%0,%1,%2,%3}, [%4];" \
        : "=r"((r)[0]), "=r"((r)[1]), "=r"((r)[2]), "=r"((r)[3]) : "r"(addr))

#define MMA16816(d, a, b0v, b1v) \
    asm volatile("mma.sync.aligned.m16n8k16.row.col.f32.f16.f16.f32 " \
        "{%0,%1,%2,%3}, {%4,%5,%6,%7}, {%8,%9}, {%0,%1,%2,%3};" \
        : "+f"((d)[0]), "+f"((d)[1]), "+f"((d)[2]), "+f"((d)[3]) \
        : "r"((a)[0]), "r"((a)[1]), "r"((a)[2]), "r"((a)[3]), "r"(b0v), "r"(b1v))

#define CPASYNC(dst, src) \
    asm volatile("cp.async.cg.shared.global [%0], [%1], 16;" :: "r"(dst), "l"(src))
#define CPCOMMIT() asm volatile("cp.async.commit_group;" ::: "memory")
#define CPWAIT1()  asm volatile("cp.async.wait_group 1;" ::: "memory")

// 1-MUFU tanh (arch-agnostic PTX, sm_75+)
__device__ __forceinline__ float fast_tanh(float x) {
    float y;
    asm("tanh.approx.f32 %0, %1;" : "=f"(y) : "f"(x));
    return y;
}

// fp32x4 -> fp16 hi/lo pairs (A is exactly hi+lo to ~2^-22)
__device__ __forceinline__ void cvt4h(float4 v, uint2& hi, uint2& lo) {
    __half2 h0 = __floats2half2_rn(v.x, v.y);
    __half2 h1 = __floats2half2_rn(v.z, v.w);
    __half2 l0 = __floats2half2_rn(v.x - __low2float(h0), v.y - __high2float(h0));
    __half2 l1 = __floats2half2_rn(v.z - __low2float(h1), v.w - __high2float(h1));
    hi = make_uint2(*(uint32_t*)&h0, *(uint32_t*)&h1);
    lo = make_uint2(*(uint32_t*)&l0, *(uint32_t*)&l1);
}

// ---------------------------------------------------------------------------
// Kernel 0 (merged): blocks [0, NB_PM) compute pm; blocks [NB_PM, +NB_W)
// convert the W1 slice to fp16.
// ---------------------------------------------------------------------------
#define W4    (HH * KBIG / 4)                // 196608 float4s
#define NB_PM ((BB * MM * HH) / 8)
#define NB_W  ((W4 + 255) / 256)

__global__ __launch_bounds__(256)
void setup_kernel(const float* __restrict__ W1, const float* __restrict__ memory,
                  const float* __restrict__ label, const float* __restrict__ b1)
{
    const int tid = threadIdx.x;
    if (blockIdx.x < NB_PM) {
        const int gw   = (blockIdx.x * 256 + tid) >> 5;
        const int lane = tid & 31;
        const int h  = gw & (HH - 1);
        const int bm = gw >> 9;
        const int b  = bm >> 3;

        const float* __restrict__ wmem = W1 + (size_t)h * WCOLS + DIM1_;
        const float* __restrict__ wlab = W1 + (size_t)h * WCOLS + KBIG;
        const float* __restrict__ mrow = memory + (size_t)bm * HH;
        const float* __restrict__ lrow = label  + (size_t)b * 512;

        float acc = 0.f;
#pragma unroll 4
        for (int d = lane; d < HH; d += 32)
            acc = fmaf(wmem[d], mrow[d], fmaf(wlab[d], lrow[d], acc));
#pragma unroll
        for (int o = 16; o; o >>= 1) acc += __shfl_xor_sync(0xFFFFFFFFu, acc, o);
        if (lane == 0) g_pm[gw] = acc + b1[h];
    } else {
        const int idx = (blockIdx.x - NB_PM) * 256 + tid;
        if (idx >= W4) return;
        const int h = idx / (KBIG / 4);
        const int k = (idx % (KBIG / 4)) * 4;
        const float4 w = *(const float4*)&W1[(size_t)h * WCOLS + k];
        __half2 a = __floats2half2_rn(w.x, w.y);
        __half2 b = __floats2half2_rn(w.z, w.w);
        *(uint2*)&g_W16[h * KBIG + k] = make_uint2(*(uint32_t*)&a, *(uint32_t*)&b);
    }
}

// ---------------------------------------------------------------------------
// GEMM (stage layout: Ahi 0 | Alo 16K | W 32K), 512 threads.
// pb = Ah*W16 + Al*W16 with fp32 accumulation (A exact, W fp16-rounded).
// ---------------------------------------------------------------------------
__device__ __forceinline__ void load_B(uint32_t sb, int tid, int colBase, int kt)
{
#pragma unroll
    for (int i = 0; i < 4; i++) {              // 256 rows x 8 slots / 512 thr
        const int v   = tid + i * 512;
        const int row = v >> 3;
        const int cs  = v & 7;
        const uint32_t off = (uint32_t)row * 128 + cs * 16;
        const uint32_t sw  = off ^ ((off >> 3) & 0x70);
        const size_t boff = (size_t)(colBase + row) * KBIG + kt * KC + cs * 8;
        CPASYNC(sb + 2 * A_TILE + sw, (const char*)&g_W16[boff]);
    }
}

__device__ __forceinline__ void load_A(float4 (&av)[4], int tid, int rowBase, int kt,
        const float* __restrict__ face, const float* __restrict__ fc,
        const float* __restrict__ img)
{
    const int f = kt >> 3;
    const float* src = (f == 0) ? face : (f == 1 ? fc : img);
    const int row = rowBase + (tid >> 2);
    const int col = (kt & 7) * KC + (tid & 3) * 16;
    const float* p = &src[(size_t)row * 512 + col];
#pragma unroll
    for (int j = 0; j < 4; j++) av[j] = *(const float4*)(p + j * 4);
}

__device__ __forceinline__ void sts_A(uint32_t sb, int tid, const float4 (&av)[4])
{
    const uint32_t rowoff = (uint32_t)(tid >> 2) * 128 + (tid & 3) * 32;
#pragma unroll
    for (int j = 0; j < 4; j++) {
        uint2 hi, lo;
        cvt4h(av[j], hi, lo);
        const uint32_t off = rowoff + j * 8;
        const uint32_t sw  = off ^ ((off >> 3) & 0x70);
        *(uint2*)(uintptr_t)__cvta_shared_to_generic(sb + sw)          = hi;
        *(uint2*)(uintptr_t)__cvta_shared_to_generic(sb + A_TILE + sw) = lo;
    }
}

__device__ __forceinline__ void mma_stage(uint32_t sb, float (&d)[4][4][4],
        int mw, int nw, int a_r, int a_kh, int b_r, int b_kh)
{
#pragma unroll
    for (int ks = 0; ks < 4; ks++) {
        const uint32_t kb = (uint32_t)(ks * 2) * 16;

        uint32_t bh[2][4];
#pragma unroll
        for (int p = 0; p < 2; p++) {
            const uint32_t off = (uint32_t)(nw * 32 + p * 16 + b_r) * 128 + kb + b_kh * 16;
            LDMX4(bh[p], sb + 2 * A_TILE + (off ^ ((off >> 3) & 0x70)));
        }
        // Ah * W
        {
            uint32_t ah[4][4];
#pragma unroll
            for (int i = 0; i < 4; i++) {
                const uint32_t off = (uint32_t)(mw * 64 + i * 16 + a_r) * 128 + kb + a_kh * 16;
                LDMX4(ah[i], sb + (off ^ ((off >> 3) & 0x70)));
            }
#pragma unroll
            for (int i = 0; i < 4; i++)
#pragma unroll
                for (int p = 0; p < 2; p++) {
                    MMA16816(d[i][2 * p],     ah[i], bh[p][0], bh[p][1]);
                    MMA16816(d[i][2 * p + 1], ah[i], bh[p][2], bh[p][3]);
                }
        }
        // Al * W
        {
            uint32_t al[4][4];
#pragma unroll
            for (int i = 0; i < 4; i++) {
                const uint32_t off = (uint32_t)(mw * 64 + i * 16 + a_r) * 128 + kb + a_kh * 16;
                LDMX4(al[i], sb + A_TILE + (off ^ ((off >> 3) & 0x70)));
            }
#pragma unroll
            for (int i = 0; i < 4; i++)
#pragma unroll
                for (int p = 0; p < 2; p++) {
                    MMA16816(d[i][2 * p],     al[i], bh[p][0], bh[p][1]);
                    MMA16816(d[i][2 * p + 1], al[i], bh[p][2], bh[p][3]);
                }
        }
    }
}

__global__ __launch_bounds__(512, 1)
void gemm_pb_mma(const float* __restrict__ face, const float* __restrict__ fc,
                 const float* __restrict__ img)
{
    extern __shared__ char dynsmem[];
    const uint32_t dynaddr = smem_u32(dynsmem);
    const uint32_t sbase = (dynaddr + 1023) & ~1023u;

    const int tid  = threadIdx.x;
    const int warp = tid >> 5;
    const int lane = tid & 31;
    const int mw = warp >> 3;            // 0..1 : m offset mw*64
    const int nw = warp & 7;             // 0..7 : n offset nw*32
    const int colBase = blockIdx.x * GN;
    const int rowBase = blockIdx.y * GM;

    const int a_r  = lane & 15;
    const int a_kh = lane >> 4;
    const int b_r  = (lane & 7) + ((lane >> 4) << 3);
    const int b_kh = (lane >> 3) & 1;

    float d[4][4][4];
#pragma unroll
    for (int i = 0; i < 4; i++)
#pragma unroll
        for (int j = 0; j < 4; j++)
#pragma unroll
            for (int q = 0; q < 4; q++) d[i][j][q] = 0.f;

    float4 av[4];
    load_A(av, tid, rowBase, 0, face, fc, img);
    load_B(sbase, tid, colBase, 0);
    CPCOMMIT();
    load_B(sbase + STAGE_BYTES, tid, colBase, 1);
    CPCOMMIT();
    sts_A(sbase, tid, av);
    load_A(av, tid, rowBase, 1, face, fc, img);

    for (int kt = 0; kt < NCH; kt++) {
        CPWAIT1();
        __syncthreads();
        if (kt + 1 < NCH) sts_A(sbase + ((kt + 1) & 1) * STAGE_BYTES, tid, av);
        if (kt + 2 < NCH) load_A(av, tid, rowBase, kt + 2, face, fc, img);
        mma_stage(sbase + (kt & 1) * STAGE_BYTES, d, mw, nw, a_r, a_kh, b_r, b_kh);
        __syncthreads();
        if (kt + 2 < NCH) load_B(sbase + (kt & 1) * STAGE_BYTES, tid, colBase, kt + 2);
        CPCOMMIT();
    }

    // Epilogue: fragment layout -> g_pb
    const int r0 = rowBase + mw * 64 + (lane >> 2);
    const int c0 = colBase + nw * 32 + (lane & 3) * 2;
#pragma unroll
    for (int i = 0; i < 4; i++)
#pragma unroll
        for (int nt = 0; nt < 4; nt++) {
            const int row = r0 + i * 16;
            const int col = c0 + nt * 8;
            *(float2*)&g_pb[(size_t)row * HH + col]       = make_float2(d[i][nt][0], d[i][nt][1]);
            *(float2*)&g_pb[(size_t)(row + 8) * HH + col] = make_float2(d[i][nt][2], d[i][nt][3]);
        }
}

// ---------------------------------------------------------------------------
// Kernel 3: e[b, m*S+s] = sum_h w2[h] * tanh(pb[b,s,h] + pm[b,m,h]).
// Warp per s; pb front-batched (MLP 16).
// ---------------------------------------------------------------------------
__global__ __launch_bounds__(256)
void e_kernel(const float* __restrict__ w2)
{
    __shared__ float pm_s[MM][HH];
    __shared__ float w2_s[HH];

    const int b   = blockIdx.y;
    const int tid = threadIdx.x;
    for (int i = tid; i < MM * HH; i += 256) ((float*)pm_s)[i] = g_pm[b * MM * HH + i];
    for (int i = tid; i < HH; i += 256)      w2_s[i] = w2[i];
    __syncthreads();

    const int warp = tid >> 5, lane = tid & 31;
    const int s = blockIdx.x * 8 + warp;
    const float* __restrict__ pb = g_pb + (size_t)(b * SS + s) * HH;

    float pv[16];
#pragma unroll
    for (int j = 0; j < 16; j++) pv[j] = pb[lane + j * 32];

    float acc[MM];
#pragma unroll
    for (int m = 0; m < MM; m++) acc[m] = 0.f;

#pragma unroll
    for (int j = 0; j < 16; j++) {
        const int h = lane + j * 32;
        const float w2v = w2_s[h];
#pragma unroll
        for (int m = 0; m < MM; m++)
            acc[m] = fmaf(w2v, fast_tanh(pv[j] + pm_s[m][h]), acc[m]);
    }
#pragma unroll
    for (int m = 0; m < MM; m++)
#pragma unroll
        for (int o = 16; o; o >>= 1) acc[m] += __shfl_xor_sync(0xFFFFFFFFu, acc[m], o);

    if (lane == 0) {
#pragma unroll
        for (int m = 0; m < MM; m++) g_e[b * MM * SS + m * SS + s] = acc[m];
    }
}

// ---------------------------------------------------------------------------
// Kernel 4: softmax over 4096, *mask, renorm; writes g_as[b][s].
// ---------------------------------------------------------------------------
__global__ __launch_bounds__(1024)
void softmax_kernel(const float* __restrict__ face_mask, float* __restrict__ alpha)
{
    __shared__ float sred[32];
    __shared__ float asum[1024];
    const int b = blockIdx.x;
    const int tid = threadIdx.x;
    const int w = tid >> 5, l = tid & 31;
    const float* __restrict__ e = g_e + b * (MM * SS);

    float v[4];
    float mx = -CUDART_INF_F;
#pragma unroll
    for (int i = 0; i < 4; i++) { v[i] = e[tid + i * 1024]; mx = fmaxf(mx, v[i]); }

#pragma unroll
    for (int o = 16; o; o >>= 1) mx = fmaxf(mx, __shfl_xor_sync(0xFFFFFFFFu, mx, o));
    if (l == 0) sred[w] = mx;
    __syncthreads();
    if (tid < 32) {
        float t = sred[tid];
#pragma unroll
        for (int o = 16; o; o >>= 1) t = fmaxf(t, __shfl_xor_sync(0xFFFFFFFFu, t, o));
        if (tid == 0) sred[0] = t;
    }
    __syncthreads();
    mx = sred[0];
    __syncthreads();

    float sum = 0.f;
#pragma unroll
    for (int i = 0; i < 4; i++) { v[i] = __expf(v[i] - mx); sum += v[i]; }
#pragma unroll
    for (int o = 16; o; o >>= 1) sum += __shfl_xor_sync(0xFFFFFFFFu, sum, o);
    if (l == 0) sred[w] = sum;
    __syncthreads();
    if (tid < 32) {
        float t = sred[tid];
#pragma unroll
        for (int o = 16; o; o >>= 1) t += __shfl_xor_sync(0xFFFFFFFFu, t, o);
        if (tid == 0) sred[0] = t;
    }
    __syncthreads();
    const float Z = sred[0];
    __syncthreads();

    const float invZ = 1.f / Z;
    float msum = 0.f;
#pragma unroll
    for (int i = 0; i < 4; i++) {
        const int idx = tid + i * 1024;
        const float mk = face_mask[b * SS + (idx & 511)];
        v[i] = v[i] * invZ * mk;
        msum += v[i];
    }
#pragma unroll
    for (int o = 16; o; o >>= 1) msum += __shfl_xor_sync(0xFFFFFFFFu, msum, o);
    if (l == 0) sred[w] = msum;
    __syncthreads();
    if (tid < 32) {
        float t = sred[tid];
#pragma unroll
        for (int o = 16; o; o >>= 1) t += __shfl_xor_sync(0xFFFFFFFFu, t, o);
        if (tid == 0) sred[0] = t;
    }
    __syncthreads();
    const float inv = 1.f / (sred[0] + EPSF);

    float part = 0.f;
#pragma unroll
    for (int i = 0; i < 4; i++) {
        const float a = v[i] * inv;
        alpha[b * (MM * SS) + tid + i * 1024] = a;
        part += a;
    }
    asum[tid] = part;
    __syncthreads();
    if (tid < 512) g_as[b * SS + tid] = asum[tid] + asum[tid + 512];
}

// ---------------------------------------------------------------------------
// Kernel 5a: context partials. Grid (4, B).
// ---------------------------------------------------------------------------
__global__ __launch_bounds__(512)
void ctx_partial_kernel(const float* __restrict__ face)
{
    __shared__ float as_s[128];
    const int q = blockIdx.x;
    const int b = blockIdx.y;
    const int tid = threadIdx.x;

    if (tid < 128) as_s[tid] = g_as[b * SS + q * 128 + tid];
    __syncthreads();

    const float* __restrict__ fb = face + (size_t)b * SS * 512 + (size_t)q * 128 * 512;
    float c0 = 0.f, c1 = 0.f, c2 = 0.f, c3 = 0.f;
#pragma unroll 4
    for (int s = 0; s < 128; s += 4) {
        c0 = fmaf(as_s[s],     fb[(size_t)s * 512 + tid],       c0);
        c1 = fmaf(as_s[s + 1], fb[(size_t)(s + 1) * 512 + tid], c1);
        c2 = fmaf(as_s[s + 2], fb[(size_t)(s + 2) * 512 + tid], c2);
        c3 = fmaf(as_s[s + 3], fb[(size_t)(s + 3) * 512 + tid], c3);
    }
    g_cp[(b * 4 + q) * 512 + tid] = (c0 + c1) + (c2 + c3);
}

// ---------------------------------------------------------------------------
// Kernel 5b: sum the 4 partials -> ctx.
// ---------------------------------------------------------------------------
__global__ __launch_bounds__(512)
void ctx_reduce_kernel(float* __restrict__ ctx)
{
    const int b = blockIdx.x;
    const int tid = threadIdx.x;
    const float* __restrict__ p = &g_cp[b * 4 * 512 + tid];
    ctx[b * 512 + tid] = (p[0] + p[512]) + (p[1024] + p[1536]);
}

// ---------------------------------------------------------------------------
// Launch. Inputs: 0 fc, 1 img, 2 label, 3 memory, 4 face, 5 face_mask,
// 6 W1, 7 b1, 8 w2.  Output: alpha [B, M*S] then context [B, DF].
// ---------------------------------------------------------------------------
extern "C" void kernel_launch(void* const* d_in, const int* in_sizes, int n_in,
                              void* d_out, int out_size)
{
    const float* fc     = (const float*)d_in[0];
    const float* img    = (const float*)d_in[1];
    const float* label  = (const float*)d_in[2];
    const float* memory = (const float*)d_in[3];
    const float* face   = (const float*)d_in[4];
    const float* fmask  = (const float*)d_in[5];
    const float* W1     = (const float*)d_in[6];
    const float* b1     = (const float*)d_in[7];
    const float* w2     = (const float*)d_in[8];

    float* out   = (float*)d_out;
    float* alpha = out;                      // [B, M*S]
    float* ctx   = out + BB * MM * SS;       // [B, DF]

    cudaFuncSetAttribute(gemm_pb_mma, cudaFuncAttributeMaxDynamicSharedMemorySize, DYN_SMEM);

    setup_kernel<<<NB_PM + NB_W, 256>>>(W1, memory, label, b1);
    gemm_pb_mma<<<dim3(HH / GN, (BB * SS) / GM), 512, DYN_SMEM>>>(face, fc, img);
    e_kernel<<<dim3(SS / 8, BB), 256>>>(w2);
    softmax_kernel<<<BB, 1024>>>(fmask, alpha);
    ctx_partial_kernel<<<dim3(4, BB), 512>>>(face);
    ctx_reduce_kernel<<<BB, 512>>>(ctx);
}

// round 13
// speedup vs baseline: 1.7991x; 1.2987x over previous
#include <cuda_runtime.h>
#include <cuda_fp16.h>
#include <math_constants.h>
#include <cstdint>

// Problem constants
#define BB    32
#define SS    512
#define MM    8
#define HH    512
#define KBIG  1536          // face|fc|img (label folded into pm)
#define DIM1_ 2048
#define WCOLS 2560
#define EPSF  1e-5f

// GEMM tiling: CTA 128x256, warp tile 64x32, 16 warps (512 threads)
#define GM 128
#define GN 256
#define KC 64                        // fp16 k per chunk = 128 B/row
#define NCH (KBIG / KC)              // 24 chunks
#define A_TILE 16384                 // 128 rows x 128 B
#define B_TILE 32768                 // 256 rows x 128 B
#define STAGE_BYTES (A_TILE + B_TILE)   // A16 | W16 = 48 KB
#define DYN_SMEM (2 * STAGE_BYTES + 1024)

// Scratch (device globals — no allocation allowed)
__device__ float g_pb[(size_t)BB * SS * HH];   // part_base [B*S, H]
__device__ float g_pm[BB * MM * HH];           // part_mem + label part + b1
__device__ float g_e [BB * MM * SS];           // logits e[b, m*S+s]
__device__ float g_as[BB * SS];                // per-s alpha sums (over m)
__device__ float g_cp[BB * 4 * 512];           // context partials
__device__ __half g_W16[HH * KBIG];            // W1 slice, fp16

__device__ __forceinline__ uint32_t smem_u32(const void* p) {
    return (uint32_t)__cvta_generic_to_shared(p);
}

#define LDMX4(r, addr) \
    asm volatile("ldmatrix.sync.aligned.m8n8.x4.shared.b16 {%0,%1,%2,%3}, [%4];" \
        : "=r"((r)[0]), "=r"((r)[1]), "=r"((r)[2]), "=r"((r)[3]) : "r"(addr))

#define MMA16816(d, a, b0v, b1v) \
    asm volatile("mma.sync.aligned.m16n8k16.row.col.f32.f16.f16.f32 " \
        "{%0,%1,%2,%3}, {%4,%5,%6,%7}, {%8,%9}, {%0,%1,%2,%3};" \
        : "+f"((d)[0]), "+f"((d)[1]), "+f"((d)[2]), "+f"((d)[3]) \
        : "r"((a)[0]), "r"((a)[1]), "r"((a)[2]), "r"((a)[3]), "r"(b0v), "r"(b1v))

#define CPASYNC(dst, src) \
    asm volatile("cp.async.cg.shared.global [%0], [%1], 16;" :: "r"(dst), "l"(src))
#define CPCOMMIT() asm volatile("cp.async.commit_group;" ::: "memory")
#define CPWAIT1()  asm volatile("cp.async.wait_group 1;" ::: "memory")

// 1-MUFU tanh (arch-agnostic PTX, sm_75+)
__device__ __forceinline__ float fast_tanh(float x) {
    float y;
    asm("tanh.approx.f32 %0, %1;" : "=f"(y) : "f"(x));
    return y;
}

// fp32x4 -> fp16x4
__device__ __forceinline__ uint2 cvt4h(float4 v) {
    __half2 h0 = __floats2half2_rn(v.x, v.y);
    __half2 h1 = __floats2half2_rn(v.z, v.w);
    return make_uint2(*(uint32_t*)&h0, *(uint32_t*)&h1);
}

// ---------------------------------------------------------------------------
// Kernel 0 (merged): blocks [0, NB_PM) compute pm; blocks [NB_PM, +NB_W)
// convert the W1 slice to fp16.
// ---------------------------------------------------------------------------
#define W4    (HH * KBIG / 4)                // 196608 float4s
#define NB_PM ((BB * MM * HH) / 8)
#define NB_W  ((W4 + 255) / 256)

__global__ __launch_bounds__(256)
void setup_kernel(const float* __restrict__ W1, const float* __restrict__ memory,
                  const float* __restrict__ label, const float* __restrict__ b1)
{
    const int tid = threadIdx.x;
    if (blockIdx.x < NB_PM) {
        const int gw   = (blockIdx.x * 256 + tid) >> 5;
        const int lane = tid & 31;
        const int h  = gw & (HH - 1);
        const int bm = gw >> 9;
        const int b  = bm >> 3;

        const float* __restrict__ wmem = W1 + (size_t)h * WCOLS + DIM1_;
        const float* __restrict__ wlab = W1 + (size_t)h * WCOLS + KBIG;
        const float* __restrict__ mrow = memory + (size_t)bm * HH;
        const float* __restrict__ lrow = label  + (size_t)b * 512;

        float acc = 0.f;
#pragma unroll 4
        for (int d = lane; d < HH; d += 32)
            acc = fmaf(wmem[d], mrow[d], fmaf(wlab[d], lrow[d], acc));
#pragma unroll
        for (int o = 16; o; o >>= 1) acc += __shfl_xor_sync(0xFFFFFFFFu, acc, o);
        if (lane == 0) g_pm[gw] = acc + b1[h];
    } else {
        const int idx = (blockIdx.x - NB_PM) * 256 + tid;
        if (idx >= W4) return;
        const int h = idx / (KBIG / 4);
        const int k = (idx % (KBIG / 4)) * 4;
        *(uint2*)&g_W16[h * KBIG + k] = cvt4h(*(const float4*)&W1[(size_t)h * WCOLS + k]);
    }
}

// ---------------------------------------------------------------------------
// GEMM (stage layout: A16 0 | W16 16K), 512 threads. Single fp16 product.
// ---------------------------------------------------------------------------
__device__ __forceinline__ void load_B(uint32_t sb, int tid, int colBase, int kt)
{
#pragma unroll
    for (int i = 0; i < 4; i++) {              // 256 rows x 8 slots / 512 thr
        const int v   = tid + i * 512;
        const int row = v >> 3;
        const int cs  = v & 7;
        const uint32_t off = (uint32_t)row * 128 + cs * 16;
        const uint32_t sw  = off ^ ((off >> 3) & 0x70);
        const size_t boff = (size_t)(colBase + row) * KBIG + kt * KC + cs * 8;
        CPASYNC(sb + A_TILE + sw, (const char*)&g_W16[boff]);
    }
}

__device__ __forceinline__ void load_A(float4 (&av)[4], int tid, int rowBase, int kt,
        const float* __restrict__ face, const float* __restrict__ fc,
        const float* __restrict__ img)
{
    const int f = kt >> 3;
    const float* src = (f == 0) ? face : (f == 1 ? fc : img);
    const int row = rowBase + (tid >> 2);
    const int col = (kt & 7) * KC + (tid & 3) * 16;
    const float* p = &src[(size_t)row * 512 + col];
#pragma unroll
    for (int j = 0; j < 4; j++) av[j] = *(const float4*)(p + j * 4);
}

__device__ __forceinline__ void sts_A(uint32_t sb, int tid, const float4 (&av)[4])
{
    const uint32_t rowoff = (uint32_t)(tid >> 2) * 128 + (tid & 3) * 32;
#pragma unroll
    for (int j = 0; j < 4; j++) {
        const uint32_t off = rowoff + j * 8;
        const uint32_t sw  = off ^ ((off >> 3) & 0x70);
        *(uint2*)(uintptr_t)__cvta_shared_to_generic(sb + sw) = cvt4h(av[j]);
    }
}

__device__ __forceinline__ void mma_stage(uint32_t sb, float (&d)[4][4][4],
        int mw, int nw, int a_r, int a_kh, int b_r, int b_kh)
{
#pragma unroll
    for (int ks = 0; ks < 4; ks++) {
        const uint32_t kb = (uint32_t)(ks * 2) * 16;

        uint32_t bh[2][4];
#pragma unroll
        for (int p = 0; p < 2; p++) {
            const uint32_t off = (uint32_t)(nw * 32 + p * 16 + b_r) * 128 + kb + b_kh * 16;
            LDMX4(bh[p], sb + A_TILE + (off ^ ((off >> 3) & 0x70)));
        }
        uint32_t ah[4][4];
#pragma unroll
        for (int i = 0; i < 4; i++) {
            const uint32_t off = (uint32_t)(mw * 64 + i * 16 + a_r) * 128 + kb + a_kh * 16;
            LDMX4(ah[i], sb + (off ^ ((off >> 3) & 0x70)));
        }
#pragma unroll
        for (int i = 0; i < 4; i++)
#pragma unroll
            for (int p = 0; p < 2; p++) {
                MMA16816(d[i][2 * p],     ah[i], bh[p][0], bh[p][1]);
                MMA16816(d[i][2 * p + 1], ah[i], bh[p][2], bh[p][3]);
            }
    }
}

__global__ __launch_bounds__(512, 1)
void gemm_pb_mma(const float* __restrict__ face, const float* __restrict__ fc,
                 const float* __restrict__ img)
{
    extern __shared__ char dynsmem[];
    const uint32_t dynaddr = smem_u32(dynsmem);
    const uint32_t sbase = (dynaddr + 1023) & ~1023u;

    const int tid  = threadIdx.x;
    const int warp = tid >> 5;
    const int lane = tid & 31;
    const int mw = warp >> 3;            // 0..1 : m offset mw*64
    const int nw = warp & 7;             // 0..7 : n offset nw*32
    const int colBase = blockIdx.x * GN;
    const int rowBase = blockIdx.y * GM;

    const int a_r  = lane & 15;
    const int a_kh = lane >> 4;
    const int b_r  = (lane & 7) + ((lane >> 4) << 3);
    const int b_kh = (lane >> 3) & 1;

    float d[4][4][4];
#pragma unroll
    for (int i = 0; i < 4; i++)
#pragma unroll
        for (int j = 0; j < 4; j++)
#pragma unroll
            for (int q = 0; q < 4; q++) d[i][j][q] = 0.f;

    float4 av[4];
    load_A(av, tid, rowBase, 0, face, fc, img);
    load_B(sbase, tid, colBase, 0);
    CPCOMMIT();
    load_B(sbase + STAGE_BYTES, tid, colBase, 1);
    CPCOMMIT();
    sts_A(sbase, tid, av);
    load_A(av, tid, rowBase, 1, face, fc, img);

    for (int kt = 0; kt < NCH; kt++) {
        CPWAIT1();
        __syncthreads();
        if (kt + 1 < NCH) sts_A(sbase + ((kt + 1) & 1) * STAGE_BYTES, tid, av);
        if (kt + 2 < NCH) load_A(av, tid, rowBase, kt + 2, face, fc, img);
        mma_stage(sbase + (kt & 1) * STAGE_BYTES, d, mw, nw, a_r, a_kh, b_r, b_kh);
        __syncthreads();
        if (kt + 2 < NCH) load_B(sbase + (kt & 1) * STAGE_BYTES, tid, colBase, kt + 2);
        CPCOMMIT();
    }

    // Epilogue: fragment layout -> g_pb
    const int r0 = rowBase + mw * 64 + (lane >> 2);
    const int c0 = colBase + nw * 32 + (lane & 3) * 2;
#pragma unroll
    for (int i = 0; i < 4; i++)
#pragma unroll
        for (int nt = 0; nt < 4; nt++) {
            const int row = r0 + i * 16;
            const int col = c0 + nt * 8;
            *(float2*)&g_pb[(size_t)row * HH + col]       = make_float2(d[i][nt][0], d[i][nt][1]);
            *(float2*)&g_pb[(size_t)(row + 8) * HH + col] = make_float2(d[i][nt][2], d[i][nt][3]);
        }
}

// ---------------------------------------------------------------------------
// Kernel 3: e[b, m*S+s] = sum_h w2[h] * tanh(pb[b,s,h] + pm[b,m,h]).
// Warp per s; pb front-batched (MLP 16).
// ---------------------------------------------------------------------------
__global__ __launch_bounds__(256)
void e_kernel(const float* __restrict__ w2)
{
    __shared__ float pm_s[MM][HH];
    __shared__ float w2_s[HH];

    const int b   = blockIdx.y;
    const int tid = threadIdx.x;
    for (int i = tid; i < MM * HH; i += 256) ((float*)pm_s)[i] = g_pm[b * MM * HH + i];
    for (int i = tid; i < HH; i += 256)      w2_s[i] = w2[i];
    __syncthreads();

    const int warp = tid >> 5, lane = tid & 31;
    const int s = blockIdx.x * 8 + warp;
    const float* __restrict__ pb = g_pb + (size_t)(b * SS + s) * HH;

    float pv[16];
#pragma unroll
    for (int j = 0; j < 16; j++) pv[j] = pb[lane + j * 32];

    float acc[MM];
#pragma unroll
    for (int m = 0; m < MM; m++) acc[m] = 0.f;

#pragma unroll
    for (int j = 0; j < 16; j++) {
        const int h = lane + j * 32;
        const float w2v = w2_s[h];
#pragma unroll
        for (int m = 0; m < MM; m++)
            acc[m] = fmaf(w2v, fast_tanh(pv[j] + pm_s[m][h]), acc[m]);
    }
#pragma unroll
    for (int m = 0; m < MM; m++)
#pragma unroll
        for (int o = 16; o; o >>= 1) acc[m] += __shfl_xor_sync(0xFFFFFFFFu, acc[m], o);

    if (lane == 0) {
#pragma unroll
        for (int m = 0; m < MM; m++) g_e[b * MM * SS + m * SS + s] = acc[m];
    }
}

// ---------------------------------------------------------------------------
// Kernel 4: softmax over 4096, *mask, renorm; writes g_as[b][s].
// ---------------------------------------------------------------------------
__global__ __launch_bounds__(1024)
void softmax_kernel(const float* __restrict__ face_mask, float* __restrict__ alpha)
{
    __shared__ float sred[32];
    __shared__ float asum[1024];
    const int b = blockIdx.x;
    const int tid = threadIdx.x;
    const int w = tid >> 5, l = tid & 31;
    const float* __restrict__ e = g_e + b * (MM * SS);

    float v[4];
    float mx = -CUDART_INF_F;
#pragma unroll
    for (int i = 0; i < 4; i++) { v[i] = e[tid + i * 1024]; mx = fmaxf(mx, v[i]); }

#pragma unroll
    for (int o = 16; o; o >>= 1) mx = fmaxf(mx, __shfl_xor_sync(0xFFFFFFFFu, mx, o));
    if (l == 0) sred[w] = mx;
    __syncthreads();
    if (tid < 32) {
        float t = sred[tid];
#pragma unroll
        for (int o = 16; o; o >>= 1) t = fmaxf(t, __shfl_xor_sync(0xFFFFFFFFu, t, o));
        if (tid == 0) sred[0] = t;
    }
    __syncthreads();
    mx = sred[0];
    __syncthreads();

    float sum = 0.f;
#pragma unroll
    for (int i = 0; i < 4; i++) { v[i] = __expf(v[i] - mx); sum += v[i]; }
#pragma unroll
    for (int o = 16; o; o >>= 1) sum += __shfl_xor_sync(0xFFFFFFFFu, sum, o);
    if (l == 0) sred[w] = sum;
    __syncthreads();
    if (tid < 32) {
        float t = sred[tid];
#pragma unroll
        for (int o = 16; o; o >>= 1) t += __shfl_xor_sync(0xFFFFFFFFu, t, o);
        if (tid == 0) sred[0] = t;
    }
    __syncthreads();
    const float Z = sred[0];
    __syncthreads();

    const float invZ = 1.f / Z;
    float msum = 0.f;
#pragma unroll
    for (int i = 0; i < 4; i++) {
        const int idx = tid + i * 1024;
        const float mk = face_mask[b * SS + (idx & 511)];
        v[i] = v[i] * invZ * mk;
        msum += v[i];
    }
#pragma unroll
    for (int o = 16; o; o >>= 1) msum += __shfl_xor_sync(0xFFFFFFFFu, msum, o);
    if (l == 0) sred[w] = msum;
    __syncthreads();
    if (tid < 32) {
        float t = sred[tid];
#pragma unroll
        for (int o = 16; o; o >>= 1) t += __shfl_xor_sync(0xFFFFFFFFu, t, o);
        if (tid == 0) sred[0] = t;
    }
    __syncthreads();
    const float inv = 1.f / (sred[0] + EPSF);

    float part = 0.f;
#pragma unroll
    for (int i = 0; i < 4; i++) {
        const float a = v[i] * inv;
        alpha[b * (MM * SS) + tid + i * 1024] = a;
        part += a;
    }
    asum[tid] = part;
    __syncthreads();
    if (tid < 512) g_as[b * SS + tid] = asum[tid] + asum[tid + 512];
}

// ---------------------------------------------------------------------------
// Kernel 5a: context partials. Grid (4, B).
// ---------------------------------------------------------------------------
__global__ __launch_bounds__(512)
void ctx_partial_kernel(const float* __restrict__ face)
{
    __shared__ float as_s[128];
    const int q = blockIdx.x;
    const int b = blockIdx.y;
    const int tid = threadIdx.x;

    if (tid < 128) as_s[tid] = g_as[b * SS + q * 128 + tid];
    __syncthreads();

    const float* __restrict__ fb = face + (size_t)b * SS * 512 + (size_t)q * 128 * 512;
    float c0 = 0.f, c1 = 0.f, c2 = 0.f, c3 = 0.f;
#pragma unroll 4
    for (int s = 0; s < 128; s += 4) {
        c0 = fmaf(as_s[s],     fb[(size_t)s * 512 + tid],       c0);
        c1 = fmaf(as_s[s + 1], fb[(size_t)(s + 1) * 512 + tid], c1);
        c2 = fmaf(as_s[s + 2], fb[(size_t)(s + 2) * 512 + tid], c2);
        c3 = fmaf(as_s[s + 3], fb[(size_t)(s + 3) * 512 + tid], c3);
    }
    g_cp[(b * 4 + q) * 512 + tid] = (c0 + c1) + (c2 + c3);
}

// ---------------------------------------------------------------------------
// Kernel 5b: sum the 4 partials -> ctx.
// ---------------------------------------------------------------------------
__global__ __launch_bounds__(512)
void ctx_reduce_kernel(float* __restrict__ ctx)
{
    const int b = blockIdx.x;
    const int tid = threadIdx.x;
    const float* __restrict__ p = &g_cp[b * 4 * 512 + tid];
    ctx[b * 512 + tid] = (p[0] + p[512]) + (p[1024] + p[1536]);
}

// ---------------------------------------------------------------------------
// Launch. Inputs: 0 fc, 1 img, 2 label, 3 memory, 4 face, 5 face_mask,
// 6 W1, 7 b1, 8 w2.  Output: alpha [B, M*S] then context [B, DF].
// ---------------------------------------------------------------------------
extern "C" void kernel_launch(void* const* d_in, const int* in_sizes, int n_in,
                              void* d_out, int out_size)
{
    const float* fc     = (const float*)d_in[0];
    const float* img    = (const float*)d_in[1];
    const float* label  = (const float*)d_in[2];
    const float* memory = (const float*)d_in[3];
    const float* face   = (const float*)d_in[4];
    const float* fmask  = (const float*)d_in[5];
    const float* W1     = (const float*)d_in[6];
    const float* b1     = (const float*)d_in[7];
    const float* w2     = (const float*)d_in[8];

    float* out   = (float*)d_out;
    float* alpha = out;                      // [B, M*S]
    float* ctx   = out + BB * MM * SS;       // [B, DF]

    cudaFuncSetAttribute(gemm_pb_mma, cudaFuncAttributeMaxDynamicSharedMemorySize, DYN_SMEM);

    setup_kernel<<<NB_PM + NB_W, 256>>>(W1, memory, label, b1);
    gemm_pb_mma<<<dim3(HH / GN, (BB * SS) / GM), 512, DYN_SMEM>>>(face, fc, img);
    e_kernel<<<dim3(SS / 8, BB), 256>>>(w2);
    softmax_kernel<<<BB, 1024>>>(fmask, alpha);
    ctx_partial_kernel<<<dim3(4, BB), 512>>>(face);
    ctx_reduce_kernel<<<BB, 512>>>(ctx);
}

// round 14
// speedup vs baseline: 1.8953x; 1.0535x over previous
#include <cuda_runtime.h>
#include <cuda_fp16.h>
#include <math_constants.h>
#include <cstdint>

// Problem constants
#define BB    32
#define SS    512
#define MM    8
#define HH    512
#define KBIG  1536          // face|fc|img (label folded into pm)
#define DIM1_ 2048
#define WCOLS 2560
#define EPSF  1e-5f

// GEMM tiling: CTA 128x256, warp tile 64x32, 16 warps (512 threads)
#define GM 128
#define GN 256
#define KC 64                        // fp16 k per chunk = 128 B/row
#define NCH (KBIG / KC)              // 24 chunks
#define A_TILE 16384                 // 128 rows x 128 B
#define B_TILE 32768                 // 256 rows x 128 B
#define STAGE_BYTES (A_TILE + B_TILE)   // A16 | W16 = 48 KB
#define NSTAGE 4
#define DYN_SMEM (NSTAGE * STAGE_BYTES + 1024)

// Scratch (device globals — no allocation allowed)
__device__ float g_pb[(size_t)BB * SS * HH];   // part_base [B*S, H]
__device__ float g_pm[BB * MM * HH];           // part_mem + label part + b1
__device__ float g_e [BB * MM * SS];           // logits e[b, m*S+s]
__device__ float g_as[BB * SS];                // per-s alpha sums (over m)
__device__ float g_cp[BB * 4 * 512];           // context partials
__device__ __half g_W16[HH * KBIG];            // W1 slice, fp16
__device__ __half g_A16[(size_t)BB * SS * KBIG]; // features, fp16, k-contiguous

__device__ __forceinline__ uint32_t smem_u32(const void* p) {
    return (uint32_t)__cvta_generic_to_shared(p);
}

#define LDMX4(r, addr) \
    asm volatile("ldmatrix.sync.aligned.m8n8.x4.shared.b16 {%0,%1,%2,%3}, [%4];" \
        : "=r"((r)[0]), "=r"((r)[1]), "=r"((r)[2]), "=r"((r)[3]) : "r"(addr))

#define MMA16816(d, a, b0v, b1v) \
    asm volatile("mma.sync.aligned.m16n8k16.row.col.f32.f16.f16.f32 " \
        "{%0,%1,%2,%3}, {%4,%5,%6,%7}, {%8,%9}, {%0,%1,%2,%3};" \
        : "+f"((d)[0]), "+f"((d)[1]), "+f"((d)[2]), "+f"((d)[3]) \
        : "r"((a)[0]), "r"((a)[1]), "r"((a)[2]), "r"((a)[3]), "r"(b0v), "r"(b1v))

#define CPASYNC(dst, src) \
    asm volatile("cp.async.cg.shared.global [%0], [%1], 16;" :: "r"(dst), "l"(src))
#define CPCOMMIT() asm volatile("cp.async.commit_group;" ::: "memory")
#define CPWAIT2()  asm volatile("cp.async.wait_group 2;" ::: "memory")

// 1-MUFU tanh (arch-agnostic PTX, sm_75+)
__device__ __forceinline__ float fast_tanh(float x) {
    float y;
    asm("tanh.approx.f32 %0, %1;" : "=f"(y) : "f"(x));
    return y;
}

// fp32x4 -> fp16x4
__device__ __forceinline__ uint2 cvt4h(float4 v) {
    __half2 h0 = __floats2half2_rn(v.x, v.y);
    __half2 h1 = __floats2half2_rn(v.z, v.w);
    return make_uint2(*(uint32_t*)&h0, *(uint32_t*)&h1);
}

// ---------------------------------------------------------------------------
// Kernel 0 (merged): pm GEMV | W1->fp16 | features->fp16 (block-range split)
// ---------------------------------------------------------------------------
#define W4    (HH * KBIG / 4)                      // 196608 float4s
#define FEAT4 ((size_t)(BB * SS) * (KBIG / 4))     // 6291456 float4s
#define NB_PM ((BB * MM * HH) / 8)
#define NB_W  (W4 / 256)
#define NB_A  ((int)(FEAT4 / 256))

__global__ __launch_bounds__(256)
void setup_kernel(const float* __restrict__ W1, const float* __restrict__ memory,
                  const float* __restrict__ label, const float* __restrict__ b1,
                  const float* __restrict__ face, const float* __restrict__ fc,
                  const float* __restrict__ img)
{
    const int tid = threadIdx.x;
    if (blockIdx.x < NB_PM) {
        const int gw   = (blockIdx.x * 256 + tid) >> 5;
        const int lane = tid & 31;
        const int h  = gw & (HH - 1);
        const int bm = gw >> 9;
        const int b  = bm >> 3;

        const float* __restrict__ wmem = W1 + (size_t)h * WCOLS + DIM1_;
        const float* __restrict__ wlab = W1 + (size_t)h * WCOLS + KBIG;
        const float* __restrict__ mrow = memory + (size_t)bm * HH;
        const float* __restrict__ lrow = label  + (size_t)b * 512;

        float acc = 0.f;
#pragma unroll 4
        for (int d = lane; d < HH; d += 32)
            acc = fmaf(wmem[d], mrow[d], fmaf(wlab[d], lrow[d], acc));
#pragma unroll
        for (int o = 16; o; o >>= 1) acc += __shfl_xor_sync(0xFFFFFFFFu, acc, o);
        if (lane == 0) g_pm[gw] = acc + b1[h];
    } else if (blockIdx.x < NB_PM + NB_W) {
        const int idx = (blockIdx.x - NB_PM) * 256 + tid;
        const int h = idx / (KBIG / 4);
        const int k = (idx % (KBIG / 4)) * 4;
        *(uint2*)&g_W16[h * KBIG + k] = cvt4h(*(const float4*)&W1[(size_t)h * WCOLS + k]);
    } else {
        const size_t idx = (size_t)(blockIdx.x - NB_PM - NB_W) * 256 + tid;
        const size_t r = idx / (KBIG / 4);
        const int    k = (int)(idx % (KBIG / 4)) * 4;
        const int    f = k >> 9;
        const float* src = ((f == 0) ? face : (f == 1 ? fc : img)) + r * 512 + (k & 511);
        *(uint2*)&g_A16[r * KBIG + k] = cvt4h(*(const float4*)src);
    }
}

// ---------------------------------------------------------------------------
// GEMM: pure cp.async mainloop, 4-stage pipeline (stage: A16 0 | W16 16K).
// ---------------------------------------------------------------------------
__device__ __forceinline__ void load_stage(uint32_t sb, int tid,
                                           int rowBase, int colBase, int kt)
{
#pragma unroll
    for (int i = 0; i < 2; i++) {              // A: 128 rows x 8 slots / 512
        const int v   = tid + i * 512;
        const int row = v >> 3;
        const int cs  = v & 7;
        const uint32_t off = (uint32_t)row * 128 + cs * 16;
        const uint32_t sw  = off ^ ((off >> 3) & 0x70);
        const size_t aoff = (size_t)(rowBase + row) * KBIG + kt * KC + cs * 8;
        CPASYNC(sb + sw, (const char*)&g_A16[aoff]);
    }
#pragma unroll
    for (int i = 0; i < 4; i++) {              // W: 256 rows x 8 slots / 512
        const int v   = tid + i * 512;
        const int row = v >> 3;
        const int cs  = v & 7;
        const uint32_t off = (uint32_t)row * 128 + cs * 16;
        const uint32_t sw  = off ^ ((off >> 3) & 0x70);
        const size_t boff = (size_t)(colBase + row) * KBIG + kt * KC + cs * 8;
        CPASYNC(sb + A_TILE + sw, (const char*)&g_W16[boff]);
    }
}

__device__ __forceinline__ void mma_stage(uint32_t sb, float (&d)[4][4][4],
        int mw, int nw, int a_r, int a_kh, int b_r, int b_kh)
{
#pragma unroll
    for (int ks = 0; ks < 4; ks++) {
        const uint32_t kb = (uint32_t)(ks * 2) * 16;

        uint32_t bh[2][4];
#pragma unroll
        for (int p = 0; p < 2; p++) {
            const uint32_t off = (uint32_t)(nw * 32 + p * 16 + b_r) * 128 + kb + b_kh * 16;
            LDMX4(bh[p], sb + A_TILE + (off ^ ((off >> 3) & 0x70)));
        }
        uint32_t ah[4][4];
#pragma unroll
        for (int i = 0; i < 4; i++) {
            const uint32_t off = (uint32_t)(mw * 64 + i * 16 + a_r) * 128 + kb + a_kh * 16;
            LDMX4(ah[i], sb + (off ^ ((off >> 3) & 0x70)));
        }
#pragma unroll
        for (int i = 0; i < 4; i++)
#pragma unroll
            for (int p = 0; p < 2; p++) {
                MMA16816(d[i][2 * p],     ah[i], bh[p][0], bh[p][1]);
                MMA16816(d[i][2 * p + 1], ah[i], bh[p][2], bh[p][3]);
            }
    }
}

__global__ __launch_bounds__(512, 1)
void gemm_pb_mma(void)
{
    extern __shared__ char dynsmem[];
    const uint32_t dynaddr = smem_u32(dynsmem);
    const uint32_t sbase = (dynaddr + 1023) & ~1023u;

    const int tid  = threadIdx.x;
    const int warp = tid >> 5;
    const int lane = tid & 31;
    const int mw = warp >> 3;            // 0..1 : m offset mw*64
    const int nw = warp & 7;             // 0..7 : n offset nw*32
    const int colBase = blockIdx.x * GN;
    const int rowBase = blockIdx.y * GM;

    const int a_r  = lane & 15;
    const int a_kh = lane >> 4;
    const int b_r  = (lane & 7) + ((lane >> 4) << 3);
    const int b_kh = (lane >> 3) & 1;

    float d[4][4][4];
#pragma unroll
    for (int i = 0; i < 4; i++)
#pragma unroll
        for (int j = 0; j < 4; j++)
#pragma unroll
            for (int q = 0; q < 4; q++) d[i][j][q] = 0.f;

    // Prologue: 3 stages in flight
#pragma unroll
    for (int p = 0; p < 3; p++) {
        load_stage(sbase + p * STAGE_BYTES, tid, rowBase, colBase, p);
        CPCOMMIT();
    }

    for (int kt = 0; kt < NCH; kt++) {
        CPWAIT2();                        // group kt complete (<=2 pending)
        __syncthreads();
        mma_stage(sbase + (kt & 3) * STAGE_BYTES, d, mw, nw, a_r, a_kh, b_r, b_kh);
        __syncthreads();
        if (kt + 3 < NCH)
            load_stage(sbase + ((kt + 3) & 3) * STAGE_BYTES, tid, rowBase, colBase, kt + 3);
        CPCOMMIT();                       // uniform group accounting
    }

    // Epilogue: fragment layout -> g_pb
    const int r0 = rowBase + mw * 64 + (lane >> 2);
    const int c0 = colBase + nw * 32 + (lane & 3) * 2;
#pragma unroll
    for (int i = 0; i < 4; i++)
#pragma unroll
        for (int nt = 0; nt < 4; nt++) {
            const int row = r0 + i * 16;
            const int col = c0 + nt * 8;
            *(float2*)&g_pb[(size_t)row * HH + col]       = make_float2(d[i][nt][0], d[i][nt][1]);
            *(float2*)&g_pb[(size_t)(row + 8) * HH + col] = make_float2(d[i][nt][2], d[i][nt][3]);
        }
}

// ---------------------------------------------------------------------------
// Kernel 3: e[b, m*S+s] = sum_h w2[h] * tanh(pb[b,s,h] + pm[b,m,h]).
// Warp per s; pb front-batched (MLP 16).
// ---------------------------------------------------------------------------
__global__ __launch_bounds__(256)
void e_kernel(const float* __restrict__ w2)
{
    __shared__ float pm_s[MM][HH];
    __shared__ float w2_s[HH];

    const int b   = blockIdx.y;
    const int tid = threadIdx.x;
    for (int i = tid; i < MM * HH; i += 256) ((float*)pm_s)[i] = g_pm[b * MM * HH + i];
    for (int i = tid; i < HH; i += 256)      w2_s[i] = w2[i];
    __syncthreads();

    const int warp = tid >> 5, lane = tid & 31;
    const int s = blockIdx.x * 8 + warp;
    const float* __restrict__ pb = g_pb + (size_t)(b * SS + s) * HH;

    float pv[16];
#pragma unroll
    for (int j = 0; j < 16; j++) pv[j] = pb[lane + j * 32];

    float acc[MM];
#pragma unroll
    for (int m = 0; m < MM; m++) acc[m] = 0.f;

#pragma unroll
    for (int j = 0; j < 16; j++) {
        const int h = lane + j * 32;
        const float w2v = w2_s[h];
#pragma unroll
        for (int m = 0; m < MM; m++)
            acc[m] = fmaf(w2v, fast_tanh(pv[j] + pm_s[m][h]), acc[m]);
    }
#pragma unroll
    for (int m = 0; m < MM; m++)
#pragma unroll
        for (int o = 16; o; o >>= 1) acc[m] += __shfl_xor_sync(0xFFFFFFFFu, acc[m], o);

    if (lane == 0) {
#pragma unroll
        for (int m = 0; m < MM; m++) g_e[b * MM * SS + m * SS + s] = acc[m];
    }
}

// ---------------------------------------------------------------------------
// Kernel 4: softmax over 4096, *mask, renorm; writes g_as[b][s].
// ---------------------------------------------------------------------------
__global__ __launch_bounds__(1024)
void softmax_kernel(const float* __restrict__ face_mask, float* __restrict__ alpha)
{
    __shared__ float sred[32];
    __shared__ float asum[1024];
    const int b = blockIdx.x;
    const int tid = threadIdx.x;
    const int w = tid >> 5, l = tid & 31;
    const float* __restrict__ e = g_e + b * (MM * SS);

    float v[4];
    float mx = -CUDART_INF_F;
#pragma unroll
    for (int i = 0; i < 4; i++) { v[i] = e[tid + i * 1024]; mx = fmaxf(mx, v[i]); }

#pragma unroll
    for (int o = 16; o; o >>= 1) mx = fmaxf(mx, __shfl_xor_sync(0xFFFFFFFFu, mx, o));
    if (l == 0) sred[w] = mx;
    __syncthreads();
    if (tid < 32) {
        float t = sred[tid];
#pragma unroll
        for (int o = 16; o; o >>= 1) t = fmaxf(t, __shfl_xor_sync(0xFFFFFFFFu, t, o));
        if (tid == 0) sred[0] = t;
    }
    __syncthreads();
    mx = sred[0];
    __syncthreads();

    float sum = 0.f;
#pragma unroll
    for (int i = 0; i < 4; i++) { v[i] = __expf(v[i] - mx); sum += v[i]; }
#pragma unroll
    for (int o = 16; o; o >>= 1) sum += __shfl_xor_sync(0xFFFFFFFFu, sum, o);
    if (l == 0) sred[w] = sum;
    __syncthreads();
    if (tid < 32) {
        float t = sred[tid];
#pragma unroll
        for (int o = 16; o; o >>= 1) t += __shfl_xor_sync(0xFFFFFFFFu, t, o);
        if (tid == 0) sred[0] = t;
    }
    __syncthreads();
    const float Z = sred[0];
    __syncthreads();

    const float invZ = 1.f / Z;
    float msum = 0.f;
#pragma unroll
    for (int i = 0; i < 4; i++) {
        const int idx = tid + i * 1024;
        const float mk = face_mask[b * SS + (idx & 511)];
        v[i] = v[i] * invZ * mk;
        msum += v[i];
    }
#pragma unroll
    for (int o = 16; o; o >>= 1) msum += __shfl_xor_sync(0xFFFFFFFFu, msum, o);
    if (l == 0) sred[w] = msum;
    __syncthreads();
    if (tid < 32) {
        float t = sred[tid];
#pragma unroll
        for (int o = 16; o; o >>= 1) t += __shfl_xor_sync(0xFFFFFFFFu, t, o);
        if (tid == 0) sred[0] = t;
    }
    __syncthreads();
    const float inv = 1.f / (sred[0] + EPSF);

    float part = 0.f;
#pragma unroll
    for (int i = 0; i < 4; i++) {
        const float a = v[i] * inv;
        alpha[b * (MM * SS) + tid + i * 1024] = a;
        part += a;
    }
    asum[tid] = part;
    __syncthreads();
    if (tid < 512) g_as[b * SS + tid] = asum[tid] + asum[tid + 512];
}

// ---------------------------------------------------------------------------
// Kernel 5a: context partials. Grid (4, B).
// ---------------------------------------------------------------------------
__global__ __launch_bounds__(512)
void ctx_partial_kernel(const float* __restrict__ face)
{
    __shared__ float as_s[128];
    const int q = blockIdx.x;
    const int b = blockIdx.y;
    const int tid = threadIdx.x;

    if (tid < 128) as_s[tid] = g_as[b * SS + q * 128 + tid];
    __syncthreads();

    const float* __restrict__ fb = face + (size_t)b * SS * 512 + (size_t)q * 128 * 512;
    float c0 = 0.f, c1 = 0.f, c2 = 0.f, c3 = 0.f;
#pragma unroll 4
    for (int s = 0; s < 128; s += 4) {
        c0 = fmaf(as_s[s],     fb[(size_t)s * 512 + tid],       c0);
        c1 = fmaf(as_s[s + 1], fb[(size_t)(s + 1) * 512 + tid], c1);
        c2 = fmaf(as_s[s + 2], fb[(size_t)(s + 2) * 512 + tid], c2);
        c3 = fmaf(as_s[s + 3], fb[(size_t)(s + 3) * 512 + tid], c3);
    }
    g_cp[(b * 4 + q) * 512 + tid] = (c0 + c1) + (c2 + c3);
}

// ---------------------------------------------------------------------------
// Kernel 5b: sum the 4 partials -> ctx.
// ---------------------------------------------------------------------------
__global__ __launch_bounds__(512)
void ctx_reduce_kernel(float* __restrict__ ctx)
{
    const int b = blockIdx.x;
    const int tid = threadIdx.x;
    const float* __restrict__ p = &g_cp[b * 4 * 512 + tid];
    ctx[b * 512 + tid] = (p[0] + p[512]) + (p[1024] + p[1536]);
}

// ---------------------------------------------------------------------------
// Launch. Inputs: 0 fc, 1 img, 2 label, 3 memory, 4 face, 5 face_mask,
// 6 W1, 7 b1, 8 w2.  Output: alpha [B, M*S] then context [B, DF].
// ---------------------------------------------------------------------------
extern "C" void kernel_launch(void* const* d_in, const int* in_sizes, int n_in,
                              void* d_out, int out_size)
{
    const float* fc     = (const float*)d_in[0];
    const float* img    = (const float*)d_in[1];
    const float* label  = (const float*)d_in[2];
    const float* memory = (const float*)d_in[3];
    const float* face   = (const float*)d_in[4];
    const float* fmask  = (const float*)d_in[5];
    const float* W1     = (const float*)d_in[6];
    const float* b1     = (const float*)d_in[7];
    const float* w2     = (const float*)d_in[8];

    float* out   = (float*)d_out;
    float* alpha = out;                      // [B, M*S]
    float* ctx   = out + BB * MM * SS;       // [B, DF]

    cudaFuncSetAttribute(gemm_pb_mma, cudaFuncAttributeMaxDynamicSharedMemorySize, DYN_SMEM);

    setup_kernel<<<NB_PM + NB_W + NB_A, 256>>>(W1, memory, label, b1, face, fc, img);
    gemm_pb_mma<<<dim3(HH / GN, (BB * SS) / GM), 512, DYN_SMEM>>>();
    e_kernel<<<dim3(SS / 8, BB), 256>>>(w2);
    softmax_kernel<<<BB, 1024>>>(fmask, alpha);
    ctx_partial_kernel<<<dim3(4, BB), 512>>>(face);
    ctx_reduce_kernel<<<BB, 512>>>(ctx);
}

// round 15
// speedup vs baseline: 1.8960x; 1.0003x over previous
#include <cuda_runtime.h>
#include <cuda_fp16.h>
#include <math_constants.h>
#include <cstdint>

// Problem constants
#define BB    32
#define SS    512
#define MM    8
#define HH    512
#define KBIG  1536          // face|fc|img (label folded into pm)
#define DIM1_ 2048
#define WCOLS 2560
#define EPSF  1e-5f

// GEMM tiling: CTA 128x128, warp tile 64x32, 8 warps (256 threads), 2 CTAs/SM
#define GM 128
#define GN 128
#define KC 64                        // fp16 k per chunk = 128 B/row
#define NCH (KBIG / KC)              // 24 chunks
#define A_TILE 16384                 // 128 rows x 128 B
#define B_TILE 16384                 // 128 rows x 128 B
#define STAGE_BYTES (A_TILE + B_TILE)   // 32 KB
#define NSTAGE 3
#define DYN_SMEM (NSTAGE * STAGE_BYTES + 1024)

// Scratch (device globals — no allocation allowed)
__device__ float g_pb[(size_t)BB * SS * HH];   // part_base [B*S, H]
__device__ float g_pm[BB * MM * HH];           // part_mem + label part + b1
__device__ float g_e [BB * MM * SS];           // logits e[b, m*S+s]
__device__ float g_as[BB * SS];                // per-s alpha sums (over m)
__device__ float g_cp[BB * 4 * 512];           // context partials
__device__ __half g_W16[HH * KBIG];            // W1 slice, fp16
__device__ __half g_A16[(size_t)BB * SS * KBIG]; // features, fp16, k-contiguous

__device__ __forceinline__ uint32_t smem_u32(const void* p) {
    return (uint32_t)__cvta_generic_to_shared(p);
}

#define LDMX4(r, addr) \
    asm volatile("ldmatrix.sync.aligned.m8n8.x4.shared.b16 {%0,%1,%2,%3}, [%4];" \
        : "=r"((r)[0]), "=r"((r)[1]), "=r"((r)[2]), "=r"((r)[3]) : "r"(addr))

#define MMA16816(d, a, b0v, b1v) \
    asm volatile("mma.sync.aligned.m16n8k16.row.col.f32.f16.f16.f32 " \
        "{%0,%1,%2,%3}, {%4,%5,%6,%7}, {%8,%9}, {%0,%1,%2,%3};" \
        : "+f"((d)[0]), "+f"((d)[1]), "+f"((d)[2]), "+f"((d)[3]) \
        : "r"((a)[0]), "r"((a)[1]), "r"((a)[2]), "r"((a)[3]), "r"(b0v), "r"(b1v))

#define CPASYNC(dst, src) \
    asm volatile("cp.async.cg.shared.global [%0], [%1], 16;" :: "r"(dst), "l"(src))
#define CPCOMMIT() asm volatile("cp.async.commit_group;" ::: "memory")
#define CPWAIT1()  asm volatile("cp.async.wait_group 1;" ::: "memory")

// 1-MUFU tanh (arch-agnostic PTX, sm_75+)
__device__ __forceinline__ float fast_tanh(float x) {
    float y;
    asm("tanh.approx.f32 %0, %1;" : "=f"(y) : "f"(x));
    return y;
}

// fp32x4 -> fp16x4
__device__ __forceinline__ uint2 cvt4h(float4 v) {
    __half2 h0 = __floats2half2_rn(v.x, v.y);
    __half2 h1 = __floats2half2_rn(v.z, v.w);
    return make_uint2(*(uint32_t*)&h0, *(uint32_t*)&h1);
}

// ---------------------------------------------------------------------------
// Kernel 0 (merged): pm GEMV | W1->fp16 | features->fp16 (block-range split)
// ---------------------------------------------------------------------------
#define W4    (HH * KBIG / 4)                      // 196608 float4s
#define FEAT4 ((size_t)(BB * SS) * (KBIG / 4))     // 6291456 float4s
#define NB_PM ((BB * MM * HH) / 8)
#define NB_W  (W4 / 256)
#define NB_A  ((int)(FEAT4 / 256))

__global__ __launch_bounds__(256)
void setup_kernel(const float* __restrict__ W1, const float* __restrict__ memory,
                  const float* __restrict__ label, const float* __restrict__ b1,
                  const float* __restrict__ face, const float* __restrict__ fc,
                  const float* __restrict__ img)
{
    const int tid = threadIdx.x;
    if (blockIdx.x < NB_PM) {
        const int gw   = (blockIdx.x * 256 + tid) >> 5;
        const int lane = tid & 31;
        const int h  = gw & (HH - 1);
        const int bm = gw >> 9;
        const int b  = bm >> 3;

        const float* __restrict__ wmem = W1 + (size_t)h * WCOLS + DIM1_;
        const float* __restrict__ wlab = W1 + (size_t)h * WCOLS + KBIG;
        const float* __restrict__ mrow = memory + (size_t)bm * HH;
        const float* __restrict__ lrow = label  + (size_t)b * 512;

        float acc = 0.f;
#pragma unroll 4
        for (int d = lane; d < HH; d += 32)
            acc = fmaf(wmem[d], mrow[d], fmaf(wlab[d], lrow[d], acc));
#pragma unroll
        for (int o = 16; o; o >>= 1) acc += __shfl_xor_sync(0xFFFFFFFFu, acc, o);
        if (lane == 0) g_pm[gw] = acc + b1[h];
    } else if (blockIdx.x < NB_PM + NB_W) {
        const int idx = (blockIdx.x - NB_PM) * 256 + tid;
        const int h = idx / (KBIG / 4);
        const int k = (idx % (KBIG / 4)) * 4;
        *(uint2*)&g_W16[h * KBIG + k] = cvt4h(*(const float4*)&W1[(size_t)h * WCOLS + k]);
    } else {
        const size_t idx = (size_t)(blockIdx.x - NB_PM - NB_W) * 256 + tid;
        const size_t r = idx / (KBIG / 4);
        const int    k = (int)(idx % (KBIG / 4)) * 4;
        const int    f = k >> 9;
        const float* src = ((f == 0) ? face : (f == 1 ? fc : img)) + r * 512 + (k & 511);
        *(uint2*)&g_A16[r * KBIG + k] = cvt4h(*(const float4*)src);
    }
}

// ---------------------------------------------------------------------------
// GEMM: pure cp.async mainloop, 3-stage pipeline (stage: A16 0 | W16 16K).
// 256 threads, 2 CTAs/SM.
// ---------------------------------------------------------------------------
__device__ __forceinline__ void load_stage(uint32_t sb, int tid,
                                           int rowBase, int colBase, int kt)
{
#pragma unroll
    for (int i = 0; i < 4; i++) {              // A: 128 rows x 8 slots / 256
        const int v   = tid + i * 256;
        const int row = v >> 3;
        const int cs  = v & 7;
        const uint32_t off = (uint32_t)row * 128 + cs * 16;
        const uint32_t sw  = off ^ ((off >> 3) & 0x70);
        const size_t aoff = (size_t)(rowBase + row) * KBIG + kt * KC + cs * 8;
        CPASYNC(sb + sw, (const char*)&g_A16[aoff]);
    }
#pragma unroll
    for (int i = 0; i < 4; i++) {              // W: 128 rows x 8 slots / 256
        const int v   = tid + i * 256;
        const int row = v >> 3;
        const int cs  = v & 7;
        const uint32_t off = (uint32_t)row * 128 + cs * 16;
        const uint32_t sw  = off ^ ((off >> 3) & 0x70);
        const size_t boff = (size_t)(colBase + row) * KBIG + kt * KC + cs * 8;
        CPASYNC(sb + A_TILE + sw, (const char*)&g_W16[boff]);
    }
}

__device__ __forceinline__ void mma_stage(uint32_t sb, float (&d)[4][4][4],
        int mw, int nw, int a_r, int a_kh, int b_r, int b_kh)
{
#pragma unroll
    for (int ks = 0; ks < 4; ks++) {
        const uint32_t kb = (uint32_t)(ks * 2) * 16;

        uint32_t bh[2][4];
#pragma unroll
        for (int p = 0; p < 2; p++) {
            const uint32_t off = (uint32_t)(nw * 32 + p * 16 + b_r) * 128 + kb + b_kh * 16;
            LDMX4(bh[p], sb + A_TILE + (off ^ ((off >> 3) & 0x70)));
        }
        uint32_t ah[4][4];
#pragma unroll
        for (int i = 0; i < 4; i++) {
            const uint32_t off = (uint32_t)(mw * 64 + i * 16 + a_r) * 128 + kb + a_kh * 16;
            LDMX4(ah[i], sb + (off ^ ((off >> 3) & 0x70)));
        }
#pragma unroll
        for (int i = 0; i < 4; i++)
#pragma unroll
            for (int p = 0; p < 2; p++) {
                MMA16816(d[i][2 * p],     ah[i], bh[p][0], bh[p][1]);
                MMA16816(d[i][2 * p + 1], ah[i], bh[p][2], bh[p][3]);
            }
    }
}

__global__ __launch_bounds__(256, 2)
void gemm_pb_mma(void)
{
    extern __shared__ char dynsmem[];
    const uint32_t dynaddr = smem_u32(dynsmem);
    const uint32_t sbase = (dynaddr + 1023) & ~1023u;

    const int tid  = threadIdx.x;
    const int warp = tid >> 5;
    const int lane = tid & 31;
    const int mw = warp >> 2;            // 0..1 : m offset mw*64
    const int nw = warp & 3;             // 0..3 : n offset nw*32
    const int colBase = blockIdx.x * GN;
    const int rowBase = blockIdx.y * GM;

    const int a_r  = lane & 15;
    const int a_kh = lane >> 4;
    const int b_r  = (lane & 7) + ((lane >> 4) << 3);
    const int b_kh = (lane >> 3) & 1;

    float d[4][4][4];
#pragma unroll
    for (int i = 0; i < 4; i++)
#pragma unroll
        for (int j = 0; j < 4; j++)
#pragma unroll
            for (int q = 0; q < 4; q++) d[i][j][q] = 0.f;

    // Prologue: 2 stages in flight
    load_stage(sbase, tid, rowBase, colBase, 0);
    CPCOMMIT();
    load_stage(sbase + STAGE_BYTES, tid, rowBase, colBase, 1);
    CPCOMMIT();

    int cur = 0;
    for (int kt = 0; kt < NCH; kt++) {
        CPWAIT1();                        // group kt complete (<=1 pending)
        __syncthreads();
        mma_stage(sbase + cur * STAGE_BYTES, d, mw, nw, a_r, a_kh, b_r, b_kh);
        __syncthreads();
        if (kt + 2 < NCH) {
            const int nxt = (cur + 2) % 3;
            load_stage(sbase + nxt * STAGE_BYTES, tid, rowBase, colBase, kt + 2);
        }
        CPCOMMIT();                       // uniform group accounting
        cur = (cur + 1) % 3;
    }

    // Epilogue: fragment layout -> g_pb
    const int r0 = rowBase + mw * 64 + (lane >> 2);
    const int c0 = colBase + nw * 32 + (lane & 3) * 2;
#pragma unroll
    for (int i = 0; i < 4; i++)
#pragma unroll
        for (int nt = 0; nt < 4; nt++) {
            const int row = r0 + i * 16;
            const int col = c0 + nt * 8;
            *(float2*)&g_pb[(size_t)row * HH + col]       = make_float2(d[i][nt][0], d[i][nt][1]);
            *(float2*)&g_pb[(size_t)(row + 8) * HH + col] = make_float2(d[i][nt][2], d[i][nt][3]);
        }
}

// ---------------------------------------------------------------------------
// Kernel 3: e[b, m*S+s] = sum_h w2[h] * tanh(pb[b,s,h] + pm[b,m,h]).
// Warp per s; pb front-batched (MLP 16).
// ---------------------------------------------------------------------------
__global__ __launch_bounds__(256)
void e_kernel(const float* __restrict__ w2)
{
    __shared__ float pm_s[MM][HH];
    __shared__ float w2_s[HH];

    const int b   = blockIdx.y;
    const int tid = threadIdx.x;
    for (int i = tid; i < MM * HH; i += 256) ((float*)pm_s)[i] = g_pm[b * MM * HH + i];
    for (int i = tid; i < HH; i += 256)      w2_s[i] = w2[i];
    __syncthreads();

    const int warp = tid >> 5, lane = tid & 31;
    const int s = blockIdx.x * 8 + warp;
    const float* __restrict__ pb = g_pb + (size_t)(b * SS + s) * HH;

    float pv[16];
#pragma unroll
    for (int j = 0; j < 16; j++) pv[j] = pb[lane + j * 32];

    float acc[MM];
#pragma unroll
    for (int m = 0; m < MM; m++) acc[m] = 0.f;

#pragma unroll
    for (int j = 0; j < 16; j++) {
        const int h = lane + j * 32;
        const float w2v = w2_s[h];
#pragma unroll
        for (int m = 0; m < MM; m++)
            acc[m] = fmaf(w2v, fast_tanh(pv[j] + pm_s[m][h]), acc[m]);
    }
#pragma unroll
    for (int m = 0; m < MM; m++)
#pragma unroll
        for (int o = 16; o; o >>= 1) acc[m] += __shfl_xor_sync(0xFFFFFFFFu, acc[m], o);

    if (lane == 0) {
#pragma unroll
        for (int m = 0; m < MM; m++) g_e[b * MM * SS + m * SS + s] = acc[m];
    }
}

// ---------------------------------------------------------------------------
// Kernel 4: softmax over 4096, *mask, renorm; writes g_as[b][s].
// ---------------------------------------------------------------------------
__global__ __launch_bounds__(1024)
void softmax_kernel(const float* __restrict__ face_mask, float* __restrict__ alpha)
{
    __shared__ float sred[32];
    __shared__ float asum[1024];
    const int b = blockIdx.x;
    const int tid = threadIdx.x;
    const int w = tid >> 5, l = tid & 31;
    const float* __restrict__ e = g_e + b * (MM * SS);

    float v[4];
    float mx = -CUDART_INF_F;
#pragma unroll
    for (int i = 0; i < 4; i++) { v[i] = e[tid + i * 1024]; mx = fmaxf(mx, v[i]); }

#pragma unroll
    for (int o = 16; o; o >>= 1) mx = fmaxf(mx, __shfl_xor_sync(0xFFFFFFFFu, mx, o));
    if (l == 0) sred[w] = mx;
    __syncthreads();
    if (tid < 32) {
        float t = sred[tid];
#pragma unroll
        for (int o = 16; o; o >>= 1) t = fmaxf(t, __shfl_xor_sync(0xFFFFFFFFu, t, o));
        if (tid == 0) sred[0] = t;
    }
    __syncthreads();
    mx = sred[0];
    __syncthreads();

    float sum = 0.f;
#pragma unroll
    for (int i = 0; i < 4; i++) { v[i] = __expf(v[i] - mx); sum += v[i]; }
#pragma unroll
    for (int o = 16; o; o >>= 1) sum += __shfl_xor_sync(0xFFFFFFFFu, sum, o);
    if (l == 0) sred[w] = sum;
    __syncthreads();
    if (tid < 32) {
        float t = sred[tid];
#pragma unroll
        for (int o = 16; o; o >>= 1) t += __shfl_xor_sync(0xFFFFFFFFu, t, o);
        if (tid == 0) sred[0] = t;
    }
    __syncthreads();
    const float Z = sred[0];
    __syncthreads();

    const float invZ = 1.f / Z;
    float msum = 0.f;
#pragma unroll
    for (int i = 0; i < 4; i++) {
        const int idx = tid + i * 1024;
        const float mk = face_mask[b * SS + (idx & 511)];
        v[i] = v[i] * invZ * mk;
        msum += v[i];
    }
#pragma unroll
    for (int o = 16; o; o >>= 1) msum += __shfl_xor_sync(0xFFFFFFFFu, msum, o);
    if (l == 0) sred[w] = msum;
    __syncthreads();
    if (tid < 32) {
        float t = sred[tid];
#pragma unroll
        for (int o = 16; o; o >>= 1) t += __shfl_xor_sync(0xFFFFFFFFu, t, o);
        if (tid == 0) sred[0] = t;
    }
    __syncthreads();
    const float inv = 1.f / (sred[0] + EPSF);

    float part = 0.f;
#pragma unroll
    for (int i = 0; i < 4; i++) {
        const float a = v[i] * inv;
        alpha[b * (MM * SS) + tid + i * 1024] = a;
        part += a;
    }
    asum[tid] = part;
    __syncthreads();
    if (tid < 512) g_as[b * SS + tid] = asum[tid] + asum[tid + 512];
}

// ---------------------------------------------------------------------------
// Kernel 5a: context partials. Grid (4, B).
// ---------------------------------------------------------------------------
__global__ __launch_bounds__(512)
void ctx_partial_kernel(const float* __restrict__ face)
{
    __shared__ float as_s[128];
    const int q = blockIdx.x;
    const int b = blockIdx.y;
    const int tid = threadIdx.x;

    if (tid < 128) as_s[tid] = g_as[b * SS + q * 128 + tid];
    __syncthreads();

    const float* __restrict__ fb = face + (size_t)b * SS * 512 + (size_t)q * 128 * 512;
    float c0 = 0.f, c1 = 0.f, c2 = 0.f, c3 = 0.f;
#pragma unroll 4
    for (int s = 0; s < 128; s += 4) {
        c0 = fmaf(as_s[s],     fb[(size_t)s * 512 + tid],       c0);
        c1 = fmaf(as_s[s + 1], fb[(size_t)(s + 1) * 512 + tid], c1);
        c2 = fmaf(as_s[s + 2], fb[(size_t)(s + 2) * 512 + tid], c2);
        c3 = fmaf(as_s[s + 3], fb[(size_t)(s + 3) * 512 + tid], c3);
    }
    g_cp[(b * 4 + q) * 512 + tid] = (c0 + c1) + (c2 + c3);
}

// ---------------------------------------------------------------------------
// Kernel 5b: sum the 4 partials -> ctx.
// ---------------------------------------------------------------------------
__global__ __launch_bounds__(512)
void ctx_reduce_kernel(float* __restrict__ ctx)
{
    const int b = blockIdx.x;
    const int tid = threadIdx.x;
    const float* __restrict__ p = &g_cp[b * 4 * 512 + tid];
    ctx[b * 512 + tid] = (p[0] + p[512]) + (p[1024] + p[1536]);
}

// ---------------------------------------------------------------------------
// Launch. Inputs: 0 fc, 1 img, 2 label, 3 memory, 4 face, 5 face_mask,
// 6 W1, 7 b1, 8 w2.  Output: alpha [B, M*S] then context [B, DF].
// ---------------------------------------------------------------------------
extern "C" void kernel_launch(void* const* d_in, const int* in_sizes, int n_in,
                              void* d_out, int out_size)
{
    const float* fc     = (const float*)d_in[0];
    const float* img    = (const float*)d_in[1];
    const float* label  = (const float*)d_in[2];
    const float* memory = (const float*)d_in[3];
    const float* face   = (const float*)d_in[4];
    const float* fmask  = (const float*)d_in[5];
    const float* W1     = (const float*)d_in[6];
    const float* b1     = (const float*)d_in[7];
    const float* w2     = (const float*)d_in[8];

    float* out   = (float*)d_out;
    float* alpha = out;                      // [B, M*S]
    float* ctx   = out + BB * MM * SS;       // [B, DF]

    cudaFuncSetAttribute(gemm_pb_mma, cudaFuncAttributeMaxDynamicSharedMemorySize, DYN_SMEM);

    setup_kernel<<<NB_PM + NB_W + NB_A, 256>>>(W1, memory, label, b1, face, fc, img);
    gemm_pb_mma<<<dim3(HH / GN, (BB * SS) / GM), 256, DYN_SMEM>>>();
    e_kernel<<<dim3(SS / 8, BB), 256>>>(w2);
    softmax_kernel<<<BB, 1024>>>(fmask, alpha);
    ctx_partial_kernel<<<dim3(4, BB), 512>>>(face);
    ctx_reduce_kernel<<<BB, 512>>>(ctx);
}

// round 16
// speedup vs baseline: 1.9025x; 1.0034x over previous
#include <cuda_runtime.h>
#include <cuda_fp16.h>
#include <math_constants.h>
#include <cstdint>

// Problem constants
#define BB    32
#define SS    512
#define MM    8
#define HH    512
#define KBIG  1536          // face|fc|img (label folded into pm)
#define DIM1_ 2048
#define WCOLS 2560
#define EPSF  1e-5f

// GEMM tiling: CTA 128x128, warp tile 64x32, 8 warps (256 threads), 2 CTAs/SM
#define GM 128
#define GN 128
#define KC 64                        // fp16 k per chunk = 128 B/row
#define NCH (KBIG / KC)              // 24 chunks
#define A_TILE 16384                 // 128 rows x 128 B
#define B_TILE 16384                 // 128 rows x 128 B
#define STAGE_BYTES (A_TILE + B_TILE)   // 32 KB
#define NSTAGE 3
#define DYN_SMEM (NSTAGE * STAGE_BYTES + 1024)

// Scratch (device globals — no allocation allowed)
__device__ float g_pb[(size_t)BB * SS * HH];   // part_base [B*S, H]
__device__ float g_pm[BB * MM * HH];           // part_mem + label part + b1
__device__ float g_e [BB * MM * SS];           // logits e[b, m*S+s]
__device__ float g_as[BB * SS];                // per-s alpha sums (over m)
__device__ float g_cp[BB * 4 * 512];           // context partials
__device__ __half g_W16[HH * KBIG];            // W1 slice, fp16
__device__ __half g_A16[(size_t)BB * SS * KBIG]; // features, fp16, k-contiguous

__device__ __forceinline__ uint32_t smem_u32(const void* p) {
    return (uint32_t)__cvta_generic_to_shared(p);
}

#define LDMX4(r, addr) \
    asm volatile("ldmatrix.sync.aligned.m8n8.x4.shared.b16 {%0,%1,%2,%3}, [%4];" \
        : "=r"((r)[0]), "=r"((r)[1]), "=r"((r)[2]), "=r"((r)[3]) : "r"(addr))

#define MMA16816(d, a, b0v, b1v) \
    asm volatile("mma.sync.aligned.m16n8k16.row.col.f32.f16.f16.f32 " \
        "{%0,%1,%2,%3}, {%4,%5,%6,%7}, {%8,%9}, {%0,%1,%2,%3};" \
        : "+f"((d)[0]), "+f"((d)[1]), "+f"((d)[2]), "+f"((d)[3]) \
        : "r"((a)[0]), "r"((a)[1]), "r"((a)[2]), "r"((a)[3]), "r"(b0v), "r"(b1v))

#define CPASYNC(dst, src) \
    asm volatile("cp.async.cg.shared.global [%0], [%1], 16;" :: "r"(dst), "l"(src))
#define CPCOMMIT() asm volatile("cp.async.commit_group;" ::: "memory")
#define CPWAIT1()  asm volatile("cp.async.wait_group 1;" ::: "memory")

// 1-MUFU tanh (arch-agnostic PTX, sm_75+)
__device__ __forceinline__ float fast_tanh(float x) {
    float y;
    asm("tanh.approx.f32 %0, %1;" : "=f"(y) : "f"(x));
    return y;
}

// fp32x4 -> fp16x4
__device__ __forceinline__ uint2 cvt4h(float4 v) {
    __half2 h0 = __floats2half2_rn(v.x, v.y);
    __half2 h1 = __floats2half2_rn(v.z, v.w);
    return make_uint2(*(uint32_t*)&h0, *(uint32_t*)&h1);
}

// ---------------------------------------------------------------------------
// Kernel 0 (merged): pm GEMV | W1->fp16 | features->fp16 (block-range split)
// ---------------------------------------------------------------------------
#define W4    (HH * KBIG / 4)                      // 196608 float4s
#define FEAT4 ((size_t)(BB * SS) * (KBIG / 4))     // 6291456 float4s
#define NB_PM ((BB * MM * HH) / 8)
#define NB_W  (W4 / 256)
#define NB_A  ((int)(FEAT4 / 256))

__global__ __launch_bounds__(256)
void setup_kernel(const float* __restrict__ W1, const float* __restrict__ memory,
                  const float* __restrict__ label, const float* __restrict__ b1,
                  const float* __restrict__ face, const float* __restrict__ fc,
                  const float* __restrict__ img)
{
    const int tid = threadIdx.x;
    if (blockIdx.x < NB_PM) {
        const int gw   = (blockIdx.x * 256 + tid) >> 5;
        const int lane = tid & 31;
        const int h  = gw & (HH - 1);
        const int bm = gw >> 9;
        const int b  = bm >> 3;

        const float* __restrict__ wmem = W1 + (size_t)h * WCOLS + DIM1_;
        const float* __restrict__ wlab = W1 + (size_t)h * WCOLS + KBIG;
        const float* __restrict__ mrow = memory + (size_t)bm * HH;
        const float* __restrict__ lrow = label  + (size_t)b * 512;

        float acc = 0.f;
#pragma unroll 4
        for (int d = lane; d < HH; d += 32)
            acc = fmaf(wmem[d], mrow[d], fmaf(wlab[d], lrow[d], acc));
#pragma unroll
        for (int o = 16; o; o >>= 1) acc += __shfl_xor_sync(0xFFFFFFFFu, acc, o);
        if (lane == 0) g_pm[gw] = acc + b1[h];
    } else if (blockIdx.x < NB_PM + NB_W) {
        const int idx = (blockIdx.x - NB_PM) * 256 + tid;
        const int h = idx / (KBIG / 4);
        const int k = (idx % (KBIG / 4)) * 4;
        *(uint2*)&g_W16[h * KBIG + k] = cvt4h(*(const float4*)&W1[(size_t)h * WCOLS + k]);
    } else {
        const size_t idx = (size_t)(blockIdx.x - NB_PM - NB_W) * 256 + tid;
        const size_t r = idx / (KBIG / 4);
        const int    k = (int)(idx % (KBIG / 4)) * 4;
        const int    f = k >> 9;
        const float* src = ((f == 0) ? face : (f == 1 ? fc : img)) + r * 512 + (k & 511);
        *(uint2*)&g_A16[r * KBIG + k] = cvt4h(*(const float4*)src);
    }
}

// ---------------------------------------------------------------------------
// GEMM: pure cp.async mainloop, 3-stage pipeline, ONE barrier per chunk.
// Stage layout: A16 0 | W16 16K. 256 threads, 2 CTAs/SM.
// ---------------------------------------------------------------------------
__device__ __forceinline__ void load_stage(uint32_t sb, int tid,
                                           int rowBase, int colBase, int kt)
{
#pragma unroll
    for (int i = 0; i < 4; i++) {              // A: 128 rows x 8 slots / 256
        const int v   = tid + i * 256;
        const int row = v >> 3;
        const int cs  = v & 7;
        const uint32_t off = (uint32_t)row * 128 + cs * 16;
        const uint32_t sw  = off ^ ((off >> 3) & 0x70);
        const size_t aoff = (size_t)(rowBase + row) * KBIG + kt * KC + cs * 8;
        CPASYNC(sb + sw, (const char*)&g_A16[aoff]);
    }
#pragma unroll
    for (int i = 0; i < 4; i++) {              // W: 128 rows x 8 slots / 256
        const int v   = tid + i * 256;
        const int row = v >> 3;
        const int cs  = v & 7;
        const uint32_t off = (uint32_t)row * 128 + cs * 16;
        const uint32_t sw  = off ^ ((off >> 3) & 0x70);
        const size_t boff = (size_t)(colBase + row) * KBIG + kt * KC + cs * 8;
        CPASYNC(sb + A_TILE + sw, (const char*)&g_W16[boff]);
    }
}

__device__ __forceinline__ void mma_stage(uint32_t sb, float (&d)[4][4][4],
        int mw, int nw, int a_r, int a_kh, int b_r, int b_kh)
{
#pragma unroll
    for (int ks = 0; ks < 4; ks++) {
        const uint32_t kb = (uint32_t)(ks * 2) * 16;

        uint32_t bh[2][4];
#pragma unroll
        for (int p = 0; p < 2; p++) {
            const uint32_t off = (uint32_t)(nw * 32 + p * 16 + b_r) * 128 + kb + b_kh * 16;
            LDMX4(bh[p], sb + A_TILE + (off ^ ((off >> 3) & 0x70)));
        }
        uint32_t ah[4][4];
#pragma unroll
        for (int i = 0; i < 4; i++) {
            const uint32_t off = (uint32_t)(mw * 64 + i * 16 + a_r) * 128 + kb + a_kh * 16;
            LDMX4(ah[i], sb + (off ^ ((off >> 3) & 0x70)));
        }
#pragma unroll
        for (int i = 0; i < 4; i++)
#pragma unroll
            for (int p = 0; p < 2; p++) {
                MMA16816(d[i][2 * p],     ah[i], bh[p][0], bh[p][1]);
                MMA16816(d[i][2 * p + 1], ah[i], bh[p][2], bh[p][3]);
            }
    }
}

__global__ __launch_bounds__(256, 2)
void gemm_pb_mma(void)
{
    extern __shared__ char dynsmem[];
    const uint32_t dynaddr = smem_u32(dynsmem);
    const uint32_t sbase = (dynaddr + 1023) & ~1023u;

    const int tid  = threadIdx.x;
    const int warp = tid >> 5;
    const int lane = tid & 31;
    const int mw = warp >> 2;            // 0..1 : m offset mw*64
    const int nw = warp & 3;             // 0..3 : n offset nw*32
    const int colBase = blockIdx.x * GN;
    const int rowBase = blockIdx.y * GM;

    const int a_r  = lane & 15;
    const int a_kh = lane >> 4;
    const int b_r  = (lane & 7) + ((lane >> 4) << 3);
    const int b_kh = (lane >> 3) & 1;

    float d[4][4][4];
#pragma unroll
    for (int i = 0; i < 4; i++)
#pragma unroll
        for (int j = 0; j < 4; j++)
#pragma unroll
            for (int q = 0; q < 4; q++) d[i][j][q] = 0.f;

    // Prologue: 2 stages in flight
    load_stage(sbase, tid, rowBase, colBase, 0);
    CPCOMMIT();
    load_stage(sbase + STAGE_BYTES, tid, rowBase, colBase, 1);
    CPCOMMIT();

    // ONE barrier per chunk. Safety: at iteration kt, the load targets stage
    // (kt+2)%3 == (kt-1)%3, consumed by mma(kt-1); every thread past this
    // iteration's barrier has finished mma(kt-1), so the overwrite is safe.
    // wait_group 1 before the barrier guarantees chunk kt's data resident.
    for (int kt = 0; kt < NCH; kt++) {
        CPWAIT1();
        __syncthreads();
        if (kt + 2 < NCH)
            load_stage(sbase + ((kt + 2) % 3) * STAGE_BYTES, tid, rowBase, colBase, kt + 2);
        CPCOMMIT();                        // uniform group accounting
        mma_stage(sbase + (kt % 3) * STAGE_BYTES, d, mw, nw, a_r, a_kh, b_r, b_kh);
    }

    // Epilogue: fragment layout -> g_pb
    const int r0 = rowBase + mw * 64 + (lane >> 2);
    const int c0 = colBase + nw * 32 + (lane & 3) * 2;
#pragma unroll
    for (int i = 0; i < 4; i++)
#pragma unroll
        for (int nt = 0; nt < 4; nt++) {
            const int row = r0 + i * 16;
            const int col = c0 + nt * 8;
            *(float2*)&g_pb[(size_t)row * HH + col]       = make_float2(d[i][nt][0], d[i][nt][1]);
            *(float2*)&g_pb[(size_t)(row + 8) * HH + col] = make_float2(d[i][nt][2], d[i][nt][3]);
        }
}

// ---------------------------------------------------------------------------
// Kernel 3: e[b, m*S+s] = sum_h w2[h] * tanh(pb[b,s,h] + pm[b,m,h]).
// Warp per s; pb front-batched (MLP 16).
// ---------------------------------------------------------------------------
__global__ __launch_bounds__(256)
void e_kernel(const float* __restrict__ w2)
{
    __shared__ float pm_s[MM][HH];
    __shared__ float w2_s[HH];

    const int b   = blockIdx.y;
    const int tid = threadIdx.x;
    for (int i = tid; i < MM * HH; i += 256) ((float*)pm_s)[i] = g_pm[b * MM * HH + i];
    for (int i = tid; i < HH; i += 256)      w2_s[i] = w2[i];
    __syncthreads();

    const int warp = tid >> 5, lane = tid & 31;
    const int s = blockIdx.x * 8 + warp;
    const float* __restrict__ pb = g_pb + (size_t)(b * SS + s) * HH;

    float pv[16];
#pragma unroll
    for (int j = 0; j < 16; j++) pv[j] = pb[lane + j * 32];

    float acc[MM];
#pragma unroll
    for (int m = 0; m < MM; m++) acc[m] = 0.f;

#pragma unroll
    for (int j = 0; j < 16; j++) {
        const int h = lane + j * 32;
        const float w2v = w2_s[h];
#pragma unroll
        for (int m = 0; m < MM; m++)
            acc[m] = fmaf(w2v, fast_tanh(pv[j] + pm_s[m][h]), acc[m]);
    }
#pragma unroll
    for (int m = 0; m < MM; m++)
#pragma unroll
        for (int o = 16; o; o >>= 1) acc[m] += __shfl_xor_sync(0xFFFFFFFFu, acc[m], o);

    if (lane == 0) {
#pragma unroll
        for (int m = 0; m < MM; m++) g_e[b * MM * SS + m * SS + s] = acc[m];
    }
}

// ---------------------------------------------------------------------------
// Kernel 4: softmax over 4096, *mask, renorm; writes g_as[b][s].
// ---------------------------------------------------------------------------
__global__ __launch_bounds__(1024)
void softmax_kernel(const float* __restrict__ face_mask, float* __restrict__ alpha)
{
    __shared__ float sred[32];
    __shared__ float asum[1024];
    const int b = blockIdx.x;
    const int tid = threadIdx.x;
    const int w = tid >> 5, l = tid & 31;
    const float* __restrict__ e = g_e + b * (MM * SS);

    float v[4];
    float mx = -CUDART_INF_F;
#pragma unroll
    for (int i = 0; i < 4; i++) { v[i] = e[tid + i * 1024]; mx = fmaxf(mx, v[i]); }

#pragma unroll
    for (int o = 16; o; o >>= 1) mx = fmaxf(mx, __shfl_xor_sync(0xFFFFFFFFu, mx, o));
    if (l == 0) sred[w] = mx;
    __syncthreads();
    if (tid < 32) {
        float t = sred[tid];
#pragma unroll
        for (int o = 16; o; o >>= 1) t = fmaxf(t, __shfl_xor_sync(0xFFFFFFFFu, t, o));
        if (tid == 0) sred[0] = t;
    }
    __syncthreads();
    mx = sred[0];
    __syncthreads();

    float sum = 0.f;
#pragma unroll
    for (int i = 0; i < 4; i++) { v[i] = __expf(v[i] - mx); sum += v[i]; }
#pragma unroll
    for (int o = 16; o; o >>= 1) sum += __shfl_xor_sync(0xFFFFFFFFu, sum, o);
    if (l == 0) sred[w] = sum;
    __syncthreads();
    if (tid < 32) {
        float t = sred[tid];
#pragma unroll
        for (int o = 16; o; o >>= 1) t += __shfl_xor_sync(0xFFFFFFFFu, t, o);
        if (tid == 0) sred[0] = t;
    }
    __syncthreads();
    const float Z = sred[0];
    __syncthreads();

    const float invZ = 1.f / Z;
    float msum = 0.f;
#pragma unroll
    for (int i = 0; i < 4; i++) {
        const int idx = tid + i * 1024;
        const float mk = face_mask[b * SS + (idx & 511)];
        v[i] = v[i] * invZ * mk;
        msum += v[i];
    }
#pragma unroll
    for (int o = 16; o; o >>= 1) msum += __shfl_xor_sync(0xFFFFFFFFu, msum, o);
    if (l == 0) sred[w] = msum;
    __syncthreads();
    if (tid < 32) {
        float t = sred[tid];
#pragma unroll
        for (int o = 16; o; o >>= 1) t += __shfl_xor_sync(0xFFFFFFFFu, t, o);
        if (tid == 0) sred[0] = t;
    }
    __syncthreads();
    const float inv = 1.f / (sred[0] + EPSF);

    float part = 0.f;
#pragma unroll
    for (int i = 0; i < 4; i++) {
        const float a = v[i] * inv;
        alpha[b * (MM * SS) + tid + i * 1024] = a;
        part += a;
    }
    asum[tid] = part;
    __syncthreads();
    if (tid < 512) g_as[b * SS + tid] = asum[tid] + asum[tid + 512];
}

// ---------------------------------------------------------------------------
// Kernel 5a: context partials. Grid (4, B).
// ---------------------------------------------------------------------------
__global__ __launch_bounds__(512)
void ctx_partial_kernel(const float* __restrict__ face)
{
    __shared__ float as_s[128];
    const int q = blockIdx.x;
    const int b = blockIdx.y;
    const int tid = threadIdx.x;

    if (tid < 128) as_s[tid] = g_as[b * SS + q * 128 + tid];
    __syncthreads();

    const float* __restrict__ fb = face + (size_t)b * SS * 512 + (size_t)q * 128 * 512;
    float c0 = 0.f, c1 = 0.f, c2 = 0.f, c3 = 0.f;
#pragma unroll 4
    for (int s = 0; s < 128; s += 4) {
        c0 = fmaf(as_s[s],     fb[(size_t)s * 512 + tid],       c0);
        c1 = fmaf(as_s[s + 1], fb[(size_t)(s + 1) * 512 + tid], c1);
        c2 = fmaf(as_s[s + 2], fb[(size_t)(s + 2) * 512 + tid], c2);
        c3 = fmaf(as_s[s + 3], fb[(size_t)(s + 3) * 512 + tid], c3);
    }
    g_cp[(b * 4 + q) * 512 + tid] = (c0 + c1) + (c2 + c3);
}

// ---------------------------------------------------------------------------
// Kernel 5b: sum the 4 partials -> ctx.
// ---------------------------------------------------------------------------
__global__ __launch_bounds__(512)
void ctx_reduce_kernel(float* __restrict__ ctx)
{
    const int b = blockIdx.x;
    const int tid = threadIdx.x;
    const float* __restrict__ p = &g_cp[b * 4 * 512 + tid];
    ctx[b * 512 + tid] = (p[0] + p[512]) + (p[1024] + p[1536]);
}

// ---------------------------------------------------------------------------
// Launch. Inputs: 0 fc, 1 img, 2 label, 3 memory, 4 face, 5 face_mask,
// 6 W1, 7 b1, 8 w2.  Output: alpha [B, M*S] then context [B, DF].
// ---------------------------------------------------------------------------
extern "C" void kernel_launch(void* const* d_in, const int* in_sizes, int n_in,
                              void* d_out, int out_size)
{
    const float* fc     = (const float*)d_in[0];
    const float* img    = (const float*)d_in[1];
    const float* label  = (const float*)d_in[2];
    const float* memory = (const float*)d_in[3];
    const float* face   = (const float*)d_in[4];
    const float* fmask  = (const float*)d_in[5];
    const float* W1     = (const float*)d_in[6];
    const float* b1     = (const float*)d_in[7];
    const float* w2     = (const float*)d_in[8];

    float* out   = (float*)d_out;
    float* alpha = out;                      // [B, M*S]
    float* ctx   = out + BB * MM * SS;       // [B, DF]

    cudaFuncSetAttribute(gemm_pb_mma, cudaFuncAttributeMaxDynamicSharedMemorySize, DYN_SMEM);

    setup_kernel<<<NB_PM + NB_W + NB_A, 256>>>(W1, memory, label, b1, face, fc, img);
    gemm_pb_mma<<<dim3(HH / GN, (BB * SS) / GM), 256, DYN_SMEM>>>();
    e_kernel<<<dim3(SS / 8, BB), 256>>>(w2);
    softmax_kernel<<<BB, 1024>>>(fmask, alpha);
    ctx_partial_kernel<<<dim3(4, BB), 512>>>(face);
    ctx_reduce_kernel<<<BB, 512>>>(ctx);
}